// round 10
// baseline (speedup 1.0000x reference)
#include <cuda_runtime.h>
#include <cuda_bf16.h>
#include <stdint.h>
#include <math.h>

// Shapes (fixed): B=4, S=2, T=1024, D=512, H=8, HD=64, M = B*S*T = 8192
// bf16 tensor-core GEMMs (mma.sync m16n8k16, fp32 accum), 2-stage cp.async.
// scores stores p=exp(logit) + partial row sums; k_zinv folds -> 1/z;
// fused AV normalizes + competitive-combines in the register fragment path
// (denominator shared between the two streams), eliminating the combine pass.

// ---------------- device workspaces ----------------
__device__ __nv_bfloat16 g_Xh[8192ull * 512];
__device__ __nv_bfloat16 g_Wh[4ull * 512 * 512];  // [Wq;Wk;Wv;Wo]
__device__ __nv_bfloat16 g_Qh[8192ull * 512];     // Q*0.125 (scale folded)
__device__ __nv_bfloat16 g_Kh[8192ull * 512];
__device__ __nv_bfloat16 g_Vh[8192ull * 512];
__device__ __nv_bfloat16 g_S[67108864ull];        // [ss][bh][q][k] unnormalized probs
__device__ float         g_zpart[524288];         // [ss][bh][nblk(8)][q]
__device__ float         g_zinv[65536];           // [ss][bh][q] 1/rowsum
__device__ __nv_bfloat16 g_attnh[8192ull * 512];
__device__ float         g_proj[8192ull * 512];

// ---------------- helpers ----------------
__device__ __forceinline__ uint32_t pack_bf16x2(float a, float b) {
    __nv_bfloat162 h = __floats2bfloat162_rn(a, b);
    return *reinterpret_cast<uint32_t*>(&h);
}

__device__ __forceinline__ void mma16816(float* c, const uint32_t* a, uint32_t b0, uint32_t b1) {
    asm volatile(
        "mma.sync.aligned.m16n8k16.row.col.f32.bf16.bf16.f32 "
        "{%0,%1,%2,%3}, {%4,%5,%6,%7}, {%8,%9}, {%0,%1,%2,%3};\n"
        : "+f"(c[0]), "+f"(c[1]), "+f"(c[2]), "+f"(c[3])
        : "r"(a[0]), "r"(a[1]), "r"(a[2]), "r"(a[3]), "r"(b0), "r"(b1));
}

__device__ __forceinline__ void cpa16(void* smem, const void* g) {
    uint32_t s = (uint32_t)__cvta_generic_to_shared(smem);
    asm volatile("cp.async.cg.shared.global [%0], [%1], 16;" :: "r"(s), "l"(g));
}
#define CPA_COMMIT asm volatile("cp.async.commit_group;")
#define CPA_WAIT0  asm volatile("cp.async.wait_group 0;")

__device__ __forceinline__ float rcp_approx(float x) {
    float r;
    asm("rcp.approx.f32 %0, %1;" : "=f"(r) : "f"(x));
    return r;
}

__device__ __forceinline__ float blk_red_sum(float v, float* sm) {
    int lane = threadIdx.x & 31, wid = threadIdx.x >> 5;
#pragma unroll
    for (int o = 16; o; o >>= 1) v += __shfl_xor_sync(0xffffffffu, v, o);
    if (lane == 0) sm[wid] = v;
    __syncthreads();
    float r = 0.f;
#pragma unroll
    for (int i = 0; i < 8; i++) r += sm[i];
    __syncthreads();
    return r;
}

// ---------------- 0) convert inputs to bf16 ----------------
__global__ __launch_bounds__(256) void k_prep(
    const float* __restrict__ X,
    const float* __restrict__ Wq, const float* __restrict__ Wk,
    const float* __restrict__ Wv, const float* __restrict__ Wo)
{
    const int idx = blockIdx.x * 256 + threadIdx.x;
    if (idx < 1048576) {
        float4 v = ((const float4*)X)[idx];
        uint2 o; o.x = pack_bf16x2(v.x, v.y); o.y = pack_bf16x2(v.z, v.w);
        ((uint2*)g_Xh)[idx] = o;
    } else {
        int j = idx - 1048576;
        int w = j >> 16;
        const float4* src = (w == 0) ? (const float4*)Wq : (w == 1) ? (const float4*)Wk
                          : (w == 2) ? (const float4*)Wv : (const float4*)Wo;
        float4 v = src[j & 65535];
        uint2 o; o.x = pack_bf16x2(v.x, v.y); o.y = pack_bf16x2(v.z, v.w);
        ((uint2*)g_Wh)[j] = o;
    }
}

// ---------------- 1) QKV projection (bf16 mma, cp.async 2-stage) ----------------
__global__ __launch_bounds__(128) void k_qkv_mma(
    const float* __restrict__ bq, const float* __restrict__ bk, const float* __restrict__ bv)
{
    __shared__ __nv_bfloat16 As[2][128][40];
    __shared__ __nv_bfloat16 Bs[2][128][40];
    const int tid = threadIdx.x, lane = tid & 31, warp = tid >> 5;
    const int wm = warp >> 1, wn = warp & 1;
    const int g = lane >> 2, t = lane & 3;
    const int m0 = blockIdx.y * 128, n0g = blockIdx.x * 128;

    const __nv_bfloat16* srcA0 = g_Xh + (size_t)(m0 + tid) * 512;
    const __nv_bfloat16* srcB0 = g_Wh + (size_t)(n0g + tid) * 512;

    float acc[4][8][4] = {};

#define QKV_ISSUE(K0, BUF)                                            \
    {                                                                 \
        _Pragma("unroll")                                             \
        for (int c = 0; c < 4; c++) {                                 \
            cpa16(&As[BUF][tid][c * 8], srcA0 + (K0) + c * 8);        \
            cpa16(&Bs[BUF][tid][c * 8], srcB0 + (K0) + c * 8);        \
        }                                                             \
    }

    QKV_ISSUE(0, 0); CPA_COMMIT;

    for (int it = 0; it < 16; it++) {
        CPA_WAIT0;
        __syncthreads();
        if (it + 1 < 16) { QKV_ISSUE((it + 1) * 32, (it + 1) & 1); CPA_COMMIT; }
        const int cb = it & 1;
#pragma unroll
        for (int kk = 0; kk < 32; kk += 16) {
            uint32_t a[4][4];
#pragma unroll
            for (int mi = 0; mi < 4; mi++)
#pragma unroll
                for (int p = 0; p < 4; p++)
                    a[mi][p] = *(const uint32_t*)&As[cb][wm * 64 + mi * 16 + ((p & 1) << 3) + g]
                                                   [kk + 2 * t + ((p >> 1) << 3)];
#pragma unroll
            for (int ni = 0; ni < 8; ni++) {
                uint32_t b0 = *(const uint32_t*)&Bs[cb][wn * 64 + ni * 8 + g][kk + 2 * t];
                uint32_t b1 = *(const uint32_t*)&Bs[cb][wn * 64 + ni * 8 + g][kk + 2 * t + 8];
#pragma unroll
                for (int mi = 0; mi < 4; mi++) mma16816(acc[mi][ni], a[mi], b0, b1);
            }
        }
        __syncthreads();
    }
#undef QKV_ISSUE

    const int mat = n0g >> 9, nloc = n0g & 511;
    const float* bias = (mat == 0) ? bq : (mat == 1) ? bk : bv;
    __nv_bfloat16* out = (mat == 0) ? g_Qh : (mat == 1) ? g_Kh : g_Vh;
    const float scale = (mat == 0) ? 0.125f : 1.0f;

#pragma unroll
    for (int mi = 0; mi < 4; mi++) {
        int r0 = m0 + wm * 64 + mi * 16 + g;
#pragma unroll
        for (int ni = 0; ni < 8; ni++) {
            int col = nloc + wn * 64 + ni * 8 + 2 * t;
            float b0f = bias[col], b1f = bias[col + 1];
            *(uint32_t*)(out + (size_t)r0 * 512 + col) =
                pack_bf16x2((acc[mi][ni][0] + b0f) * scale, (acc[mi][ni][1] + b1f) * scale);
            *(uint32_t*)(out + (size_t)(r0 + 8) * 512 + col) =
                pack_bf16x2((acc[mi][ni][2] + b0f) * scale, (acc[mi][ni][3] + b1f) * scale);
        }
    }
}

// ---------------- 2) scores: p = exp(Qs_ss @ K_{1-ss}^T) + partial row sums ----
__global__ __launch_bounds__(128) void k_scores_mma()
{
    __shared__ __nv_bfloat16 As[2][128][40];
    __shared__ __nv_bfloat16 Bs[2][128][40];
    __shared__ float zs[128][2];
    const int z = blockIdx.z;
    const int ss = z >> 5, bh = z & 31, b = bh >> 3, h = bh & 7;
    const __nv_bfloat16* Abase = g_Qh + ((size_t)(b * 2 + ss) * 1024) * 512 + h * 64;
    const __nv_bfloat16* Bbase = g_Kh + ((size_t)(b * 2 + (1 - ss)) * 1024) * 512 + h * 64;
    __nv_bfloat16* C = g_S + ((size_t)z << 20);

    const int tid = threadIdx.x, lane = tid & 31, warp = tid >> 5;
    const int wm = warp >> 1, wn = warp & 1;
    const int g = lane >> 2, t = lane & 3;
    const int m0 = blockIdx.y * 128, n0 = blockIdx.x * 128;

    const __nv_bfloat16* srcA0 = Abase + (size_t)(m0 + tid) * 512;
    const __nv_bfloat16* srcB0 = Bbase + (size_t)(n0 + tid) * 512;

    float acc[4][8][4] = {};

#define SC_ISSUE(K0, BUF)                                             \
    {                                                                 \
        _Pragma("unroll")                                             \
        for (int c = 0; c < 4; c++) {                                 \
            cpa16(&As[BUF][tid][c * 8], srcA0 + (K0) + c * 8);        \
            cpa16(&Bs[BUF][tid][c * 8], srcB0 + (K0) + c * 8);        \
        }                                                             \
    }

    SC_ISSUE(0, 0); CPA_COMMIT;

    for (int it = 0; it < 2; it++) {
        CPA_WAIT0;
        __syncthreads();
        if (it + 1 < 2) { SC_ISSUE(32, 1); CPA_COMMIT; }
        const int cb = it & 1;
#pragma unroll
        for (int kk = 0; kk < 32; kk += 16) {
            uint32_t a[4][4];
#pragma unroll
            for (int mi = 0; mi < 4; mi++)
#pragma unroll
                for (int p = 0; p < 4; p++)
                    a[mi][p] = *(const uint32_t*)&As[cb][wm * 64 + mi * 16 + ((p & 1) << 3) + g]
                                                   [kk + 2 * t + ((p >> 1) << 3)];
#pragma unroll
            for (int ni = 0; ni < 8; ni++) {
                uint32_t b0 = *(const uint32_t*)&Bs[cb][wn * 64 + ni * 8 + g][kk + 2 * t];
                uint32_t b1 = *(const uint32_t*)&Bs[cb][wn * 64 + ni * 8 + g][kk + 2 * t + 8];
#pragma unroll
                for (int mi = 0; mi < 4; mi++) mma16816(acc[mi][ni], a[mi], b0, b1);
            }
        }
        __syncthreads();
    }
#undef SC_ISSUE

#pragma unroll
    for (int mi = 0; mi < 4; mi++) {
        size_t r0 = m0 + wm * 64 + mi * 16 + g;
        float rs0 = 0.f, rs1 = 0.f;
#pragma unroll
        for (int ni = 0; ni < 8; ni++) {
            float e0 = __expf(acc[mi][ni][0]);
            float e1 = __expf(acc[mi][ni][1]);
            float e2 = __expf(acc[mi][ni][2]);
            float e3 = __expf(acc[mi][ni][3]);
            rs0 += e0 + e1;  rs1 += e2 + e3;
            int col = n0 + wn * 64 + ni * 8 + 2 * t;
            *(uint32_t*)(C + r0 * 1024 + col) = pack_bf16x2(e0, e1);
            *(uint32_t*)(C + (r0 + 8) * 1024 + col) = pack_bf16x2(e2, e3);
        }
#pragma unroll
        for (int o = 1; o < 4; o <<= 1) {
            rs0 += __shfl_xor_sync(0xffffffffu, rs0, o);
            rs1 += __shfl_xor_sync(0xffffffffu, rs1, o);
        }
        if (t == 0) {
            zs[wm * 64 + mi * 16 + g][wn]     = rs0;
            zs[wm * 64 + mi * 16 + g + 8][wn] = rs1;
        }
    }
    __syncthreads();
    if (tid < 128) {
        float zsum = zs[tid][0] + zs[tid][1];
        g_zpart[((size_t)z * 8 + blockIdx.x) * 1024 + m0 + tid] = zsum;
    }
}

// ---------------- 3) fold partial sums -> reciprocal ----------------
__global__ __launch_bounds__(512) void k_zinv()
{
    const int i = blockIdx.x * 512 + threadIdx.x;
    const int z = i >> 10, q = i & 1023;
    float s = 0.f;
#pragma unroll
    for (int nb = 0; nb < 8; nb++) s += g_zpart[((size_t)z * 8 + nb) * 1024 + q];
    g_zinv[i] = __fdividef(1.f, s);
}

// ---------------- 4) fused normalize + compete + AV (both streams) ----------------
// grid (8, 32): x = 128-row tile, y = bh. 256 threads = 8 warps; warp w owns
// rows [w*16, w*16+16) and all 64 head-dims for BOTH streams. P tiles arrive
// unnormalized via cp.async; the combine math happens on register fragments
// (denominator shared between streams, pairwise-rcp).
__global__ __launch_bounds__(256, 2) void k_av_fused()
{
    __shared__ __nv_bfloat16 P1s[2][128][40];
    __shared__ __nv_bfloat16 P2s[2][128][40];
    __shared__ __nv_bfloat16 V1s[2][64][40];   // [dim][tok]
    __shared__ __nv_bfloat16 V2s[2][64][40];
    __shared__ float i1s[128], i2s[128];

    const int bh = blockIdx.y, b = bh >> 3, h = bh & 7;
    const int m0 = blockIdx.x * 128;
    const __nv_bfloat16* P12 = g_S + ((size_t)bh << 20);
    const __nv_bfloat16* P21 = g_S + 33554432ull + ((size_t)bh << 20);
    const __nv_bfloat16* V1 = g_Vh + ((size_t)(b * 2 + 0) * 1024) * 512 + h * 64;
    const __nv_bfloat16* V2 = g_Vh + ((size_t)(b * 2 + 1) * 1024) * 512 + h * 64;
    __nv_bfloat16* C1 = g_attnh + ((size_t)(b * 2 + 0) * 1024) * 512 + h * 64;  // A12 @ V2
    __nv_bfloat16* C2 = g_attnh + ((size_t)(b * 2 + 1) * 1024) * 512 + h * 64;  // A21 @ V1

    const int tid = threadIdx.x, lane = tid & 31, warp = tid >> 5;
    const int g = lane >> 2, t = lane & 3;

    if (tid < 128) {
        i1s[tid] = g_zinv[bh * 1024 + m0 + tid];
        i2s[tid] = g_zinv[32768 + bh * 1024 + m0 + tid];
    }
    __syncthreads();
    const float i1a = i1s[warp * 16 + g],     i1b = i1s[warp * 16 + 8 + g];
    const float i2a = i2s[warp * 16 + g],     i2b = i2s[warp * 16 + 8 + g];

    // cp.async thread mapping for P tiles: row = tid>>1, two 16B chunks
    const int prow = tid >> 1, pseg = (tid & 1) * 16;
    const __nv_bfloat16* srcP1 = P12 + (size_t)(m0 + prow) * 1024 + pseg;
    const __nv_bfloat16* srcP2 = P21 + (size_t)(m0 + prow) * 1024 + pseg;
    // V register-pipeline mapping
    const int kr = tid >> 3, dseg = (tid & 7) * 8;
    const __nv_bfloat16* srcV1 = V1 + (size_t)kr * 512 + dseg;
    const __nv_bfloat16* srcV2 = V2 + (size_t)kr * 512 + dseg;

    float acc1[8][4] = {}, acc2[8][4] = {};
    __nv_bfloat16 vr1[8], vr2[8];

#define FAV_ISSUE_P(K0, BUF)                                          \
    {                                                                 \
        cpa16(&P1s[BUF][prow][pseg],     srcP1 + (K0));               \
        cpa16(&P1s[BUF][prow][pseg + 8], srcP1 + (K0) + 8);           \
        cpa16(&P2s[BUF][prow][pseg],     srcP2 + (K0));               \
        cpa16(&P2s[BUF][prow][pseg + 8], srcP2 + (K0) + 8);           \
    }
#define FAV_LD_V(K0)                                                  \
    {                                                                 \
        *(uint4*)vr1 = *(const uint4*)(srcV1 + (size_t)(K0) * 512);   \
        *(uint4*)vr2 = *(const uint4*)(srcV2 + (size_t)(K0) * 512);   \
    }
#define FAV_ST_V(BUF)                                                 \
    {                                                                 \
        _Pragma("unroll")                                             \
        for (int j = 0; j < 8; j++) {                                 \
            V1s[BUF][dseg + j][kr] = vr1[j];                          \
            V2s[BUF][dseg + j][kr] = vr2[j];                          \
        }                                                             \
    }

    FAV_ISSUE_P(0, 0); CPA_COMMIT;
    FAV_LD_V(0); FAV_ST_V(0);
    FAV_LD_V(32);

    for (int it = 0; it < 32; it++) {
        CPA_WAIT0;
        __syncthreads();
        if (it + 1 < 32) { FAV_ISSUE_P((it + 1) * 32, (it + 1) & 1); CPA_COMMIT; }
        const int cb = it & 1;
#pragma unroll
        for (int kk = 0; kk < 32; kk += 16) {
            // raw fragments (both streams), then normalize+combine in regs
            uint32_t na1[4], na2[4];
#pragma unroll
            for (int p = 0; p < 4; p++) {
                const int row = warp * 16 + ((p & 1) << 3) + g;
                const int kcol = kk + 2 * t + ((p >> 1) << 3);
                uint32_t r1 = *(const uint32_t*)&P1s[cb][row][kcol];
                uint32_t r2 = *(const uint32_t*)&P2s[cb][row][kcol];
                __nv_bfloat162 h1 = *reinterpret_cast<__nv_bfloat162*>(&r1);
                __nv_bfloat162 h2 = *reinterpret_cast<__nv_bfloat162*>(&r2);
                const float ii1 = (p & 1) ? i1b : i1a;
                const float ii2 = (p & 1) ? i2b : i2a;
                float s1lo = __bfloat162float(h1.x) * ii1;
                float s1hi = __bfloat162float(h1.y) * ii1;
                float s2lo = __bfloat162float(h2.x) * ii2;
                float s2hi = __bfloat162float(h2.y) * ii2;
                float dlo = s1lo + s2lo + 1e-6f;
                float dhi = s1hi + s2hi + 1e-6f;
                float r = rcp_approx(dlo * dhi);
                float invlo = r * dhi, invhi = r * dlo;
                na1[p] = pack_bf16x2(s1lo * invlo, s1hi * invhi);
                na2[p] = pack_bf16x2(s2lo * invlo, s2hi * invhi);
            }
#pragma unroll
            for (int ni = 0; ni < 8; ni++) {
                const int cbase = ni * 8 + g;
                uint32_t b20 = *(const uint32_t*)&V2s[cb][cbase][kk + 2 * t];
                uint32_t b21 = *(const uint32_t*)&V2s[cb][cbase][kk + 2 * t + 8];
                mma16816(acc1[ni], na1, b20, b21);
                uint32_t b10 = *(const uint32_t*)&V1s[cb][cbase][kk + 2 * t];
                uint32_t b11 = *(const uint32_t*)&V1s[cb][cbase][kk + 2 * t + 8];
                mma16816(acc2[ni], na2, b10, b11);
            }
        }
        if (it + 1 < 32) {
            FAV_ST_V((it + 1) & 1);
            if (it + 2 < 32) FAV_LD_V((it + 2) * 32);
        }
    }
#undef FAV_ISSUE_P
#undef FAV_LD_V
#undef FAV_ST_V

    const int r0 = m0 + warp * 16 + g;
#pragma unroll
    for (int ni = 0; ni < 8; ni++) {
        int col = ni * 8 + 2 * t;
        *(uint32_t*)(C1 + (size_t)r0 * 512 + col)       = pack_bf16x2(acc1[ni][0], acc1[ni][1]);
        *(uint32_t*)(C1 + (size_t)(r0 + 8) * 512 + col) = pack_bf16x2(acc1[ni][2], acc1[ni][3]);
        *(uint32_t*)(C2 + (size_t)r0 * 512 + col)       = pack_bf16x2(acc2[ni][0], acc2[ni][1]);
        *(uint32_t*)(C2 + (size_t)(r0 + 8) * 512 + col) = pack_bf16x2(acc2[ni][2], acc2[ni][3]);
    }
}

// ---------------- 5) output projection: g_proj = attn @ Wo^T + bo ----------------
__global__ __launch_bounds__(128) void k_out_mma(const float* __restrict__ bo)
{
    __shared__ __nv_bfloat16 As[2][128][40];
    __shared__ __nv_bfloat16 Bs[2][128][40];
    const int tid = threadIdx.x, lane = tid & 31, warp = tid >> 5;
    const int wm = warp >> 1, wn = warp & 1;
    const int g = lane >> 2, t = lane & 3;
    const int m0 = blockIdx.y * 128, n0 = blockIdx.x * 128;
    const __nv_bfloat16* Wo = g_Wh + 3ull * 512 * 512;

    const __nv_bfloat16* srcA0 = g_attnh + (size_t)(m0 + tid) * 512;
    const __nv_bfloat16* srcB0 = Wo + (size_t)(n0 + tid) * 512;

    float acc[4][8][4] = {};

#define OUT_ISSUE(K0, BUF)                                            \
    {                                                                 \
        _Pragma("unroll")                                             \
        for (int c = 0; c < 4; c++) {                                 \
            cpa16(&As[BUF][tid][c * 8], srcA0 + (K0) + c * 8);        \
            cpa16(&Bs[BUF][tid][c * 8], srcB0 + (K0) + c * 8);        \
        }                                                             \
    }

    OUT_ISSUE(0, 0); CPA_COMMIT;

    for (int it = 0; it < 16; it++) {
        CPA_WAIT0;
        __syncthreads();
        if (it + 1 < 16) { OUT_ISSUE((it + 1) * 32, (it + 1) & 1); CPA_COMMIT; }
        const int cb = it & 1;
#pragma unroll
        for (int kk = 0; kk < 32; kk += 16) {
            uint32_t a[4][4];
#pragma unroll
            for (int mi = 0; mi < 4; mi++)
#pragma unroll
                for (int p = 0; p < 4; p++)
                    a[mi][p] = *(const uint32_t*)&As[cb][wm * 64 + mi * 16 + ((p & 1) << 3) + g]
                                                   [kk + 2 * t + ((p >> 1) << 3)];
#pragma unroll
            for (int ni = 0; ni < 8; ni++) {
                uint32_t b0 = *(const uint32_t*)&Bs[cb][wn * 64 + ni * 8 + g][kk + 2 * t];
                uint32_t b1 = *(const uint32_t*)&Bs[cb][wn * 64 + ni * 8 + g][kk + 2 * t + 8];
#pragma unroll
                for (int mi = 0; mi < 4; mi++) mma16816(acc[mi][ni], a[mi], b0, b1);
            }
        }
        __syncthreads();
    }
#undef OUT_ISSUE

#pragma unroll
    for (int mi = 0; mi < 4; mi++) {
        int r0 = m0 + wm * 64 + mi * 16 + g;
#pragma unroll
        for (int ni = 0; ni < 8; ni++) {
            int col = n0 + wn * 64 + ni * 8 + 2 * t;
            float b0f = bo[col], b1f = bo[col + 1];
            *(float2*)(g_proj + (size_t)r0 * 512 + col) =
                make_float2(acc[mi][ni][0] + b0f, acc[mi][ni][1] + b1f);
            *(float2*)(g_proj + (size_t)(r0 + 8) * 512 + col) =
                make_float2(acc[mi][ni][2] + b0f, acc[mi][ni][3] + b1f);
        }
    }
}

// ---------------- 6) LayerNorm + gate + residual ----------------
__global__ __launch_bounds__(256) void k_ln(
    const float* __restrict__ hidden,
    const float* __restrict__ ln_g, const float* __restrict__ ln_b,
    const float* __restrict__ alpha, float* __restrict__ out)
{
    const int m = blockIdx.x;
    const int s = (m >> 10) & 1;
    const float* p = g_proj + (size_t)m * 512;
    const int tid = threadIdx.x;
    __shared__ float sm[8];

    float x0 = p[tid], x1 = p[tid + 256];
    float sum = blk_red_sum(x0 + x1, sm);
    float sq  = blk_red_sum(x0 * x0 + x1 * x1, sm);
    float mu  = sum * (1.f / 512.f);
    float var = sq * (1.f / 512.f) - mu * mu;
    float rstd = rsqrtf(var + 1e-5f);
    float al = alpha[s];
    size_t base = (size_t)m * 512;

    {
        int e = tid;
        float y = (x0 - mu) * rstd * ln_g[s * 512 + e] + ln_b[s * 512 + e];
        out[base + e] = hidden[base + e] + y * al;
    }
    {
        int e = tid + 256;
        float y = (x1 - mu) * rstd * ln_g[s * 512 + e] + ln_b[s * 512 + e];
        out[base + e] = hidden[base + e] + y * al;
    }
}

// ---------------- launch ----------------
extern "C" void kernel_launch(void* const* d_in, const int* in_sizes, int n_in,
                              void* d_out, int out_size)
{
    const float* hidden = (const float*)d_in[0];
    const float* Wq = (const float*)d_in[1];  const float* bq = (const float*)d_in[2];
    const float* Wk = (const float*)d_in[3];  const float* bk = (const float*)d_in[4];
    const float* Wv = (const float*)d_in[5];  const float* bv = (const float*)d_in[6];
    const float* Wo = (const float*)d_in[7];  const float* bo = (const float*)d_in[8];
    const float* lng = (const float*)d_in[9]; const float* lnb = (const float*)d_in[10];
    const float* alpha = (const float*)d_in[11];
    float* out = (float*)d_out;

    k_prep<<<5120, 256>>>(hidden, Wq, Wk, Wv, Wo);
    k_qkv_mma<<<dim3(12, 64), 128>>>(bq, bk, bv);
    k_scores_mma<<<dim3(8, 8, 64), 128>>>();
    k_zinv<<<128, 512>>>();
    k_av_fused<<<dim3(8, 32), 256>>>();
    k_out_mma<<<dim3(4, 64), 128>>>(bo);
    k_ln<<<8192, 256>>>(hidden, lng, lnb, alpha, out);
}

// round 11
// speedup vs baseline: 1.4761x; 1.4761x over previous
#include <cuda_runtime.h>
#include <cuda_bf16.h>
#include <stdint.h>
#include <math.h>

// Shapes (fixed): B=4, S=2, T=1024, D=512, H=8, HD=64, M = B*S*T = 8192
// bf16 tensor-core GEMMs (mma.sync m16n8k16, fp32 accum), 2-stage cp.async.
// scores stores p=exp(logit) + partial row sums; k_zinv folds -> 1/z;
// fused AV normalizes + competitive-combines on register fragments
// (64-row tiles, 128 threads, no reg cap -> no spills; 2 CTAs/SM).

// ---------------- device workspaces ----------------
__device__ __nv_bfloat16 g_Xh[8192ull * 512];
__device__ __nv_bfloat16 g_Wh[4ull * 512 * 512];  // [Wq;Wk;Wv;Wo]
__device__ __nv_bfloat16 g_Qh[8192ull * 512];     // Q*0.125 (scale folded)
__device__ __nv_bfloat16 g_Kh[8192ull * 512];
__device__ __nv_bfloat16 g_Vh[8192ull * 512];
__device__ __nv_bfloat16 g_S[67108864ull];        // [ss][bh][q][k] unnormalized probs
__device__ float         g_zpart[524288];         // [ss][bh][nblk(8)][q]
__device__ float         g_zinv[65536];           // [ss][bh][q] 1/rowsum
__device__ __nv_bfloat16 g_attnh[8192ull * 512];
__device__ float         g_proj[8192ull * 512];

// ---------------- helpers ----------------
__device__ __forceinline__ uint32_t pack_bf16x2(float a, float b) {
    __nv_bfloat162 h = __floats2bfloat162_rn(a, b);
    return *reinterpret_cast<uint32_t*>(&h);
}

__device__ __forceinline__ void mma16816(float* c, const uint32_t* a, uint32_t b0, uint32_t b1) {
    asm volatile(
        "mma.sync.aligned.m16n8k16.row.col.f32.bf16.bf16.f32 "
        "{%0,%1,%2,%3}, {%4,%5,%6,%7}, {%8,%9}, {%0,%1,%2,%3};\n"
        : "+f"(c[0]), "+f"(c[1]), "+f"(c[2]), "+f"(c[3])
        : "r"(a[0]), "r"(a[1]), "r"(a[2]), "r"(a[3]), "r"(b0), "r"(b1));
}

__device__ __forceinline__ void cpa16(void* smem, const void* g) {
    uint32_t s = (uint32_t)__cvta_generic_to_shared(smem);
    asm volatile("cp.async.cg.shared.global [%0], [%1], 16;" :: "r"(s), "l"(g));
}
#define CPA_COMMIT asm volatile("cp.async.commit_group;")
#define CPA_WAIT0  asm volatile("cp.async.wait_group 0;")

__device__ __forceinline__ float rcp_approx(float x) {
    float r;
    asm("rcp.approx.f32 %0, %1;" : "=f"(r) : "f"(x));
    return r;
}

__device__ __forceinline__ float blk_red_sum(float v, float* sm) {
    int lane = threadIdx.x & 31, wid = threadIdx.x >> 5;
#pragma unroll
    for (int o = 16; o; o >>= 1) v += __shfl_xor_sync(0xffffffffu, v, o);
    if (lane == 0) sm[wid] = v;
    __syncthreads();
    float r = 0.f;
#pragma unroll
    for (int i = 0; i < 8; i++) r += sm[i];
    __syncthreads();
    return r;
}

// ---------------- 0) convert inputs to bf16 ----------------
__global__ __launch_bounds__(256) void k_prep(
    const float* __restrict__ X,
    const float* __restrict__ Wq, const float* __restrict__ Wk,
    const float* __restrict__ Wv, const float* __restrict__ Wo)
{
    const int idx = blockIdx.x * 256 + threadIdx.x;
    if (idx < 1048576) {
        float4 v = ((const float4*)X)[idx];
        uint2 o; o.x = pack_bf16x2(v.x, v.y); o.y = pack_bf16x2(v.z, v.w);
        ((uint2*)g_Xh)[idx] = o;
    } else {
        int j = idx - 1048576;
        int w = j >> 16;
        const float4* src = (w == 0) ? (const float4*)Wq : (w == 1) ? (const float4*)Wk
                          : (w == 2) ? (const float4*)Wv : (const float4*)Wo;
        float4 v = src[j & 65535];
        uint2 o; o.x = pack_bf16x2(v.x, v.y); o.y = pack_bf16x2(v.z, v.w);
        ((uint2*)g_Wh)[j] = o;
    }
}

// ---------------- 1) QKV projection (bf16 mma, cp.async 2-stage) ----------------
__global__ __launch_bounds__(128) void k_qkv_mma(
    const float* __restrict__ bq, const float* __restrict__ bk, const float* __restrict__ bv)
{
    __shared__ __nv_bfloat16 As[2][128][40];
    __shared__ __nv_bfloat16 Bs[2][128][40];
    const int tid = threadIdx.x, lane = tid & 31, warp = tid >> 5;
    const int wm = warp >> 1, wn = warp & 1;
    const int g = lane >> 2, t = lane & 3;
    const int m0 = blockIdx.y * 128, n0g = blockIdx.x * 128;

    const __nv_bfloat16* srcA0 = g_Xh + (size_t)(m0 + tid) * 512;
    const __nv_bfloat16* srcB0 = g_Wh + (size_t)(n0g + tid) * 512;

    float acc[4][8][4] = {};

#define QKV_ISSUE(K0, BUF)                                            \
    {                                                                 \
        _Pragma("unroll")                                             \
        for (int c = 0; c < 4; c++) {                                 \
            cpa16(&As[BUF][tid][c * 8], srcA0 + (K0) + c * 8);        \
            cpa16(&Bs[BUF][tid][c * 8], srcB0 + (K0) + c * 8);        \
        }                                                             \
    }

    QKV_ISSUE(0, 0); CPA_COMMIT;

    for (int it = 0; it < 16; it++) {
        CPA_WAIT0;
        __syncthreads();
        if (it + 1 < 16) { QKV_ISSUE((it + 1) * 32, (it + 1) & 1); CPA_COMMIT; }
        const int cb = it & 1;
#pragma unroll
        for (int kk = 0; kk < 32; kk += 16) {
            uint32_t a[4][4];
#pragma unroll
            for (int mi = 0; mi < 4; mi++)
#pragma unroll
                for (int p = 0; p < 4; p++)
                    a[mi][p] = *(const uint32_t*)&As[cb][wm * 64 + mi * 16 + ((p & 1) << 3) + g]
                                                   [kk + 2 * t + ((p >> 1) << 3)];
#pragma unroll
            for (int ni = 0; ni < 8; ni++) {
                uint32_t b0 = *(const uint32_t*)&Bs[cb][wn * 64 + ni * 8 + g][kk + 2 * t];
                uint32_t b1 = *(const uint32_t*)&Bs[cb][wn * 64 + ni * 8 + g][kk + 2 * t + 8];
#pragma unroll
                for (int mi = 0; mi < 4; mi++) mma16816(acc[mi][ni], a[mi], b0, b1);
            }
        }
        __syncthreads();
    }
#undef QKV_ISSUE

    const int mat = n0g >> 9, nloc = n0g & 511;
    const float* bias = (mat == 0) ? bq : (mat == 1) ? bk : bv;
    __nv_bfloat16* out = (mat == 0) ? g_Qh : (mat == 1) ? g_Kh : g_Vh;
    const float scale = (mat == 0) ? 0.125f : 1.0f;

#pragma unroll
    for (int mi = 0; mi < 4; mi++) {
        int r0 = m0 + wm * 64 + mi * 16 + g;
#pragma unroll
        for (int ni = 0; ni < 8; ni++) {
            int col = nloc + wn * 64 + ni * 8 + 2 * t;
            float b0f = bias[col], b1f = bias[col + 1];
            *(uint32_t*)(out + (size_t)r0 * 512 + col) =
                pack_bf16x2((acc[mi][ni][0] + b0f) * scale, (acc[mi][ni][1] + b1f) * scale);
            *(uint32_t*)(out + (size_t)(r0 + 8) * 512 + col) =
                pack_bf16x2((acc[mi][ni][2] + b0f) * scale, (acc[mi][ni][3] + b1f) * scale);
        }
    }
}

// ---------------- 2) scores: p = exp(Qs_ss @ K_{1-ss}^T) + partial row sums ----
__global__ __launch_bounds__(128) void k_scores_mma()
{
    __shared__ __nv_bfloat16 As[2][128][40];
    __shared__ __nv_bfloat16 Bs[2][128][40];
    __shared__ float zs[128][2];
    const int z = blockIdx.z;
    const int ss = z >> 5, bh = z & 31, b = bh >> 3, h = bh & 7;
    const __nv_bfloat16* Abase = g_Qh + ((size_t)(b * 2 + ss) * 1024) * 512 + h * 64;
    const __nv_bfloat16* Bbase = g_Kh + ((size_t)(b * 2 + (1 - ss)) * 1024) * 512 + h * 64;
    __nv_bfloat16* C = g_S + ((size_t)z << 20);

    const int tid = threadIdx.x, lane = tid & 31, warp = tid >> 5;
    const int wm = warp >> 1, wn = warp & 1;
    const int g = lane >> 2, t = lane & 3;
    const int m0 = blockIdx.y * 128, n0 = blockIdx.x * 128;

    const __nv_bfloat16* srcA0 = Abase + (size_t)(m0 + tid) * 512;
    const __nv_bfloat16* srcB0 = Bbase + (size_t)(n0 + tid) * 512;

    float acc[4][8][4] = {};

#define SC_ISSUE(K0, BUF)                                             \
    {                                                                 \
        _Pragma("unroll")                                             \
        for (int c = 0; c < 4; c++) {                                 \
            cpa16(&As[BUF][tid][c * 8], srcA0 + (K0) + c * 8);        \
            cpa16(&Bs[BUF][tid][c * 8], srcB0 + (K0) + c * 8);        \
        }                                                             \
    }

    SC_ISSUE(0, 0); CPA_COMMIT;

    for (int it = 0; it < 2; it++) {
        CPA_WAIT0;
        __syncthreads();
        if (it + 1 < 2) { SC_ISSUE(32, 1); CPA_COMMIT; }
        const int cb = it & 1;
#pragma unroll
        for (int kk = 0; kk < 32; kk += 16) {
            uint32_t a[4][4];
#pragma unroll
            for (int mi = 0; mi < 4; mi++)
#pragma unroll
                for (int p = 0; p < 4; p++)
                    a[mi][p] = *(const uint32_t*)&As[cb][wm * 64 + mi * 16 + ((p & 1) << 3) + g]
                                                   [kk + 2 * t + ((p >> 1) << 3)];
#pragma unroll
            for (int ni = 0; ni < 8; ni++) {
                uint32_t b0 = *(const uint32_t*)&Bs[cb][wn * 64 + ni * 8 + g][kk + 2 * t];
                uint32_t b1 = *(const uint32_t*)&Bs[cb][wn * 64 + ni * 8 + g][kk + 2 * t + 8];
#pragma unroll
                for (int mi = 0; mi < 4; mi++) mma16816(acc[mi][ni], a[mi], b0, b1);
            }
        }
        __syncthreads();
    }
#undef SC_ISSUE

#pragma unroll
    for (int mi = 0; mi < 4; mi++) {
        size_t r0 = m0 + wm * 64 + mi * 16 + g;
        float rs0 = 0.f, rs1 = 0.f;
#pragma unroll
        for (int ni = 0; ni < 8; ni++) {
            float e0 = __expf(acc[mi][ni][0]);
            float e1 = __expf(acc[mi][ni][1]);
            float e2 = __expf(acc[mi][ni][2]);
            float e3 = __expf(acc[mi][ni][3]);
            rs0 += e0 + e1;  rs1 += e2 + e3;
            int col = n0 + wn * 64 + ni * 8 + 2 * t;
            *(uint32_t*)(C + r0 * 1024 + col) = pack_bf16x2(e0, e1);
            *(uint32_t*)(C + (r0 + 8) * 1024 + col) = pack_bf16x2(e2, e3);
        }
#pragma unroll
        for (int o = 1; o < 4; o <<= 1) {
            rs0 += __shfl_xor_sync(0xffffffffu, rs0, o);
            rs1 += __shfl_xor_sync(0xffffffffu, rs1, o);
        }
        if (t == 0) {
            zs[wm * 64 + mi * 16 + g][wn]     = rs0;
            zs[wm * 64 + mi * 16 + g + 8][wn] = rs1;
        }
    }
    __syncthreads();
    if (tid < 128) {
        float zsum = zs[tid][0] + zs[tid][1];
        g_zpart[((size_t)z * 8 + blockIdx.x) * 1024 + m0 + tid] = zsum;
    }
}

// ---------------- 3) fold partial sums -> reciprocal ----------------
__global__ __launch_bounds__(512) void k_zinv()
{
    const int i = blockIdx.x * 512 + threadIdx.x;
    const int z = i >> 10, q = i & 1023;
    float s = 0.f;
#pragma unroll
    for (int nb = 0; nb < 8; nb++) s += g_zpart[((size_t)z * 8 + nb) * 1024 + q];
    g_zinv[i] = __fdividef(1.f, s);
}

// ---------------- 4) fused normalize + compete + AV (both streams) ----------------
// grid (16, 32): x = 64-row tile, y = bh. 128 threads = 4 warps; warp w owns
// rows [w*16, w*16+16) of BOTH streams. No reg cap (no spills); 2 CTAs/SM.
__global__ __launch_bounds__(128) void k_av_fused()
{
    __shared__ __nv_bfloat16 P1s[2][64][40];
    __shared__ __nv_bfloat16 P2s[2][64][40];
    __shared__ __nv_bfloat16 V1s[2][64][40];   // [dim][tok]
    __shared__ __nv_bfloat16 V2s[2][64][40];
    __shared__ float i1s[64], i2s[64];

    const int bh = blockIdx.y, b = bh >> 3, h = bh & 7;
    const int m0 = blockIdx.x * 64;
    const __nv_bfloat16* P12 = g_S + ((size_t)bh << 20);
    const __nv_bfloat16* P21 = g_S + 33554432ull + ((size_t)bh << 20);
    const __nv_bfloat16* V1 = g_Vh + ((size_t)(b * 2 + 0) * 1024) * 512 + h * 64;
    const __nv_bfloat16* V2 = g_Vh + ((size_t)(b * 2 + 1) * 1024) * 512 + h * 64;
    __nv_bfloat16* C1 = g_attnh + ((size_t)(b * 2 + 0) * 1024) * 512 + h * 64;  // A12 @ V2
    __nv_bfloat16* C2 = g_attnh + ((size_t)(b * 2 + 1) * 1024) * 512 + h * 64;  // A21 @ V1

    const int tid = threadIdx.x, lane = tid & 31, warp = tid >> 5;
    const int g = lane >> 2, t = lane & 3;

    if (tid < 64) {
        i1s[tid] = g_zinv[bh * 1024 + m0 + tid];
        i2s[tid] = g_zinv[32768 + bh * 1024 + m0 + tid];
    }
    __syncthreads();
    const float i1a = i1s[warp * 16 + g],     i1b = i1s[warp * 16 + 8 + g];
    const float i2a = i2s[warp * 16 + g],     i2b = i2s[warp * 16 + 8 + g];

    // cp.async mapping for P tiles (64 rows x 32 cols): row = tid>>1, 2x16B
    const int prow = tid >> 1, pseg = (tid & 1) * 16;
    const __nv_bfloat16* srcP1 = P12 + (size_t)(m0 + prow) * 1024 + pseg;
    const __nv_bfloat16* srcP2 = P21 + (size_t)(m0 + prow) * 1024 + pseg;
    // V register pipeline (32 tok x 64 dim): kr = tid>>2, 16 dims each
    const int kr = tid >> 2, dseg = (tid & 3) * 16;
    const __nv_bfloat16* srcV1 = V1 + (size_t)kr * 512 + dseg;
    const __nv_bfloat16* srcV2 = V2 + (size_t)kr * 512 + dseg;

    float acc1[8][4] = {}, acc2[8][4] = {};
    __nv_bfloat16 vr1[16], vr2[16];

#define FAV_ISSUE_P(K0, BUF)                                          \
    {                                                                 \
        cpa16(&P1s[BUF][prow][pseg],     srcP1 + (K0));               \
        cpa16(&P1s[BUF][prow][pseg + 8], srcP1 + (K0) + 8);           \
        cpa16(&P2s[BUF][prow][pseg],     srcP2 + (K0));               \
        cpa16(&P2s[BUF][prow][pseg + 8], srcP2 + (K0) + 8);           \
    }
#define FAV_LD_V(K0)                                                  \
    {                                                                 \
        const __nv_bfloat16* s1 = srcV1 + (size_t)(K0) * 512;         \
        const __nv_bfloat16* s2 = srcV2 + (size_t)(K0) * 512;         \
        *(uint4*)vr1       = *(const uint4*)s1;                       \
        *(uint4*)(vr1 + 8) = *(const uint4*)(s1 + 8);                 \
        *(uint4*)vr2       = *(const uint4*)s2;                       \
        *(uint4*)(vr2 + 8) = *(const uint4*)(s2 + 8);                 \
    }
#define FAV_ST_V(BUF)                                                 \
    {                                                                 \
        _Pragma("unroll")                                             \
        for (int j = 0; j < 16; j++) {                                \
            V1s[BUF][dseg + j][kr] = vr1[j];                          \
            V2s[BUF][dseg + j][kr] = vr2[j];                          \
        }                                                             \
    }

    FAV_ISSUE_P(0, 0); CPA_COMMIT;
    FAV_LD_V(0); FAV_ST_V(0);
    FAV_LD_V(32);

    for (int it = 0; it < 32; it++) {
        CPA_WAIT0;
        __syncthreads();
        if (it + 1 < 32) { FAV_ISSUE_P((it + 1) * 32, (it + 1) & 1); CPA_COMMIT; }
        const int cb = it & 1;
#pragma unroll
        for (int kk = 0; kk < 32; kk += 16) {
            uint32_t na1[4], na2[4];
#pragma unroll
            for (int p = 0; p < 4; p++) {
                const int row = warp * 16 + ((p & 1) << 3) + g;
                const int kcol = kk + 2 * t + ((p >> 1) << 3);
                uint32_t r1 = *(const uint32_t*)&P1s[cb][row][kcol];
                uint32_t r2 = *(const uint32_t*)&P2s[cb][row][kcol];
                __nv_bfloat162 h1 = *reinterpret_cast<__nv_bfloat162*>(&r1);
                __nv_bfloat162 h2 = *reinterpret_cast<__nv_bfloat162*>(&r2);
                const float ii1 = (p & 1) ? i1b : i1a;
                const float ii2 = (p & 1) ? i2b : i2a;
                float s1lo = __bfloat162float(h1.x) * ii1;
                float s1hi = __bfloat162float(h1.y) * ii1;
                float s2lo = __bfloat162float(h2.x) * ii2;
                float s2hi = __bfloat162float(h2.y) * ii2;
                float dlo = s1lo + s2lo + 1e-6f;
                float dhi = s1hi + s2hi + 1e-6f;
                float r = rcp_approx(dlo * dhi);
                float invlo = r * dhi, invhi = r * dlo;
                na1[p] = pack_bf16x2(s1lo * invlo, s1hi * invhi);
                na2[p] = pack_bf16x2(s2lo * invlo, s2hi * invhi);
            }
#pragma unroll
            for (int ni = 0; ni < 8; ni++) {
                const int cbase = ni * 8 + g;
                uint32_t b20 = *(const uint32_t*)&V2s[cb][cbase][kk + 2 * t];
                uint32_t b21 = *(const uint32_t*)&V2s[cb][cbase][kk + 2 * t + 8];
                mma16816(acc1[ni], na1, b20, b21);
                uint32_t b10 = *(const uint32_t*)&V1s[cb][cbase][kk + 2 * t];
                uint32_t b11 = *(const uint32_t*)&V1s[cb][cbase][kk + 2 * t + 8];
                mma16816(acc2[ni], na2, b10, b11);
            }
        }
        if (it + 1 < 32) {
            FAV_ST_V((it + 1) & 1);
            if (it + 2 < 32) FAV_LD_V((it + 2) * 32);
        }
    }
#undef FAV_ISSUE_P
#undef FAV_LD_V
#undef FAV_ST_V

    const int r0 = m0 + warp * 16 + g;
#pragma unroll
    for (int ni = 0; ni < 8; ni++) {
        int col = ni * 8 + 2 * t;
        *(uint32_t*)(C1 + (size_t)r0 * 512 + col)       = pack_bf16x2(acc1[ni][0], acc1[ni][1]);
        *(uint32_t*)(C1 + (size_t)(r0 + 8) * 512 + col) = pack_bf16x2(acc1[ni][2], acc1[ni][3]);
        *(uint32_t*)(C2 + (size_t)r0 * 512 + col)       = pack_bf16x2(acc2[ni][0], acc2[ni][1]);
        *(uint32_t*)(C2 + (size_t)(r0 + 8) * 512 + col) = pack_bf16x2(acc2[ni][2], acc2[ni][3]);
    }
}

// ---------------- 5) output projection: g_proj = attn @ Wo^T + bo ----------------
__global__ __launch_bounds__(128) void k_out_mma(const float* __restrict__ bo)
{
    __shared__ __nv_bfloat16 As[2][128][40];
    __shared__ __nv_bfloat16 Bs[2][128][40];
    const int tid = threadIdx.x, lane = tid & 31, warp = tid >> 5;
    const int wm = warp >> 1, wn = warp & 1;
    const int g = lane >> 2, t = lane & 3;
    const int m0 = blockIdx.y * 128, n0 = blockIdx.x * 128;
    const __nv_bfloat16* Wo = g_Wh + 3ull * 512 * 512;

    const __nv_bfloat16* srcA0 = g_attnh + (size_t)(m0 + tid) * 512;
    const __nv_bfloat16* srcB0 = Wo + (size_t)(n0 + tid) * 512;

    float acc[4][8][4] = {};

#define OUT_ISSUE(K0, BUF)                                            \
    {                                                                 \
        _Pragma("unroll")                                             \
        for (int c = 0; c < 4; c++) {                                 \
            cpa16(&As[BUF][tid][c * 8], srcA0 + (K0) + c * 8);        \
            cpa16(&Bs[BUF][tid][c * 8], srcB0 + (K0) + c * 8);        \
        }                                                             \
    }

    OUT_ISSUE(0, 0); CPA_COMMIT;

    for (int it = 0; it < 16; it++) {
        CPA_WAIT0;
        __syncthreads();
        if (it + 1 < 16) { OUT_ISSUE((it + 1) * 32, (it + 1) & 1); CPA_COMMIT; }
        const int cb = it & 1;
#pragma unroll
        for (int kk = 0; kk < 32; kk += 16) {
            uint32_t a[4][4];
#pragma unroll
            for (int mi = 0; mi < 4; mi++)
#pragma unroll
                for (int p = 0; p < 4; p++)
                    a[mi][p] = *(const uint32_t*)&As[cb][wm * 64 + mi * 16 + ((p & 1) << 3) + g]
                                                   [kk + 2 * t + ((p >> 1) << 3)];
#pragma unroll
            for (int ni = 0; ni < 8; ni++) {
                uint32_t b0 = *(const uint32_t*)&Bs[cb][wn * 64 + ni * 8 + g][kk + 2 * t];
                uint32_t b1 = *(const uint32_t*)&Bs[cb][wn * 64 + ni * 8 + g][kk + 2 * t + 8];
#pragma unroll
                for (int mi = 0; mi < 4; mi++) mma16816(acc[mi][ni], a[mi], b0, b1);
            }
        }
        __syncthreads();
    }
#undef OUT_ISSUE

#pragma unroll
    for (int mi = 0; mi < 4; mi++) {
        int r0 = m0 + wm * 64 + mi * 16 + g;
#pragma unroll
        for (int ni = 0; ni < 8; ni++) {
            int col = n0 + wn * 64 + ni * 8 + 2 * t;
            float b0f = bo[col], b1f = bo[col + 1];
            *(float2*)(g_proj + (size_t)r0 * 512 + col) =
                make_float2(acc[mi][ni][0] + b0f, acc[mi][ni][1] + b1f);
            *(float2*)(g_proj + (size_t)(r0 + 8) * 512 + col) =
                make_float2(acc[mi][ni][2] + b0f, acc[mi][ni][3] + b1f);
        }
    }
}

// ---------------- 6) LayerNorm + gate + residual ----------------
__global__ __launch_bounds__(256) void k_ln(
    const float* __restrict__ hidden,
    const float* __restrict__ ln_g, const float* __restrict__ ln_b,
    const float* __restrict__ alpha, float* __restrict__ out)
{
    const int m = blockIdx.x;
    const int s = (m >> 10) & 1;
    const float* p = g_proj + (size_t)m * 512;
    const int tid = threadIdx.x;
    __shared__ float sm[8];

    float x0 = p[tid], x1 = p[tid + 256];
    float sum = blk_red_sum(x0 + x1, sm);
    float sq  = blk_red_sum(x0 * x0 + x1 * x1, sm);
    float mu  = sum * (1.f / 512.f);
    float var = sq * (1.f / 512.f) - mu * mu;
    float rstd = rsqrtf(var + 1e-5f);
    float al = alpha[s];
    size_t base = (size_t)m * 512;

    {
        int e = tid;
        float y = (x0 - mu) * rstd * ln_g[s * 512 + e] + ln_b[s * 512 + e];
        out[base + e] = hidden[base + e] + y * al;
    }
    {
        int e = tid + 256;
        float y = (x1 - mu) * rstd * ln_g[s * 512 + e] + ln_b[s * 512 + e];
        out[base + e] = hidden[base + e] + y * al;
    }
}

// ---------------- launch ----------------
extern "C" void kernel_launch(void* const* d_in, const int* in_sizes, int n_in,
                              void* d_out, int out_size)
{
    const float* hidden = (const float*)d_in[0];
    const float* Wq = (const float*)d_in[1];  const float* bq = (const float*)d_in[2];
    const float* Wk = (const float*)d_in[3];  const float* bk = (const float*)d_in[4];
    const float* Wv = (const float*)d_in[5];  const float* bv = (const float*)d_in[6];
    const float* Wo = (const float*)d_in[7];  const float* bo = (const float*)d_in[8];
    const float* lng = (const float*)d_in[9]; const float* lnb = (const float*)d_in[10];
    const float* alpha = (const float*)d_in[11];
    float* out = (float*)d_out;

    k_prep<<<5120, 256>>>(hidden, Wq, Wk, Wv, Wo);
    k_qkv_mma<<<dim3(12, 64), 128>>>(bq, bk, bv);
    k_scores_mma<<<dim3(8, 8, 64), 128>>>();
    k_zinv<<<128, 512>>>();
    k_av_fused<<<dim3(16, 32), 128>>>();
    k_out_mma<<<dim3(4, 64), 128>>>(bo);
    k_ln<<<8192, 256>>>(hidden, lng, lnb, alpha, out);
}

// round 12
// speedup vs baseline: 1.5457x; 1.0472x over previous
#include <cuda_runtime.h>
#include <cuda_bf16.h>
#include <stdint.h>
#include <math.h>

// Shapes (fixed): B=4, S=2, T=1024, D=512, H=8, HD=64, M = B*S*T = 8192
// bf16 tensor-core GEMMs (mma.sync m16n8k16, fp32 accum), 2-stage cp.async.
// Flash-style attention: pass1 (k_rowsum) computes z[q]=sum exp(logit) only;
// pass2 (k_attn_fused) recomputes score fragments in registers, normalizes +
// competitive-combines on the C->A fragment repack, and runs AV — the score
// matrix never touches memory.

// ---------------- device workspaces ----------------
__device__ __nv_bfloat16 g_Xh[8192ull * 512];
__device__ __nv_bfloat16 g_Wh[4ull * 512 * 512];  // [Wq;Wk;Wv;Wo]
__device__ __nv_bfloat16 g_Qh[8192ull * 512];     // Q*0.125 (scale folded)
__device__ __nv_bfloat16 g_Kh[8192ull * 512];
__device__ __nv_bfloat16 g_Vh[8192ull * 512];
__device__ float         g_zpart[524288];         // [ss][bh][nblk(8)][q]
__device__ float         g_zinv[65536];           // [ss][bh][q] 1/rowsum
__device__ __nv_bfloat16 g_attnh[8192ull * 512];
__device__ float         g_proj[8192ull * 512];

// ---------------- helpers ----------------
__device__ __forceinline__ uint32_t pack_bf16x2(float a, float b) {
    __nv_bfloat162 h = __floats2bfloat162_rn(a, b);
    return *reinterpret_cast<uint32_t*>(&h);
}

__device__ __forceinline__ void mma16816(float* c, const uint32_t* a, uint32_t b0, uint32_t b1) {
    asm volatile(
        "mma.sync.aligned.m16n8k16.row.col.f32.bf16.bf16.f32 "
        "{%0,%1,%2,%3}, {%4,%5,%6,%7}, {%8,%9}, {%0,%1,%2,%3};\n"
        : "+f"(c[0]), "+f"(c[1]), "+f"(c[2]), "+f"(c[3])
        : "r"(a[0]), "r"(a[1]), "r"(a[2]), "r"(a[3]), "r"(b0), "r"(b1));
}

__device__ __forceinline__ void cpa16(void* smem, const void* g) {
    uint32_t s = (uint32_t)__cvta_generic_to_shared(smem);
    asm volatile("cp.async.cg.shared.global [%0], [%1], 16;" :: "r"(s), "l"(g));
}
#define CPA_COMMIT asm volatile("cp.async.commit_group;")
#define CPA_WAIT0  asm volatile("cp.async.wait_group 0;")

__device__ __forceinline__ float rcp_approx(float x) {
    float r;
    asm("rcp.approx.f32 %0, %1;" : "=f"(r) : "f"(x));
    return r;
}

__device__ __forceinline__ float blk_red_sum(float v, float* sm) {
    int lane = threadIdx.x & 31, wid = threadIdx.x >> 5;
#pragma unroll
    for (int o = 16; o; o >>= 1) v += __shfl_xor_sync(0xffffffffu, v, o);
    if (lane == 0) sm[wid] = v;
    __syncthreads();
    float r = 0.f;
#pragma unroll
    for (int i = 0; i < 8; i++) r += sm[i];
    __syncthreads();
    return r;
}

// ---------------- 0) convert inputs to bf16 ----------------
__global__ __launch_bounds__(256) void k_prep(
    const float* __restrict__ X,
    const float* __restrict__ Wq, const float* __restrict__ Wk,
    const float* __restrict__ Wv, const float* __restrict__ Wo)
{
    const int idx = blockIdx.x * 256 + threadIdx.x;
    if (idx < 1048576) {
        float4 v = ((const float4*)X)[idx];
        uint2 o; o.x = pack_bf16x2(v.x, v.y); o.y = pack_bf16x2(v.z, v.w);
        ((uint2*)g_Xh)[idx] = o;
    } else {
        int j = idx - 1048576;
        int w = j >> 16;
        const float4* src = (w == 0) ? (const float4*)Wq : (w == 1) ? (const float4*)Wk
                          : (w == 2) ? (const float4*)Wv : (const float4*)Wo;
        float4 v = src[j & 65535];
        uint2 o; o.x = pack_bf16x2(v.x, v.y); o.y = pack_bf16x2(v.z, v.w);
        ((uint2*)g_Wh)[j] = o;
    }
}

// ---------------- 1) QKV projection (bf16 mma, cp.async 2-stage) ----------------
__global__ __launch_bounds__(128) void k_qkv_mma(
    const float* __restrict__ bq, const float* __restrict__ bk, const float* __restrict__ bv)
{
    __shared__ __nv_bfloat16 As[2][128][40];
    __shared__ __nv_bfloat16 Bs[2][128][40];
    const int tid = threadIdx.x, lane = tid & 31, warp = tid >> 5;
    const int wm = warp >> 1, wn = warp & 1;
    const int g = lane >> 2, t = lane & 3;
    const int m0 = blockIdx.y * 128, n0g = blockIdx.x * 128;

    const __nv_bfloat16* srcA0 = g_Xh + (size_t)(m0 + tid) * 512;
    const __nv_bfloat16* srcB0 = g_Wh + (size_t)(n0g + tid) * 512;

    float acc[4][8][4] = {};

#define QKV_ISSUE(K0, BUF)                                            \
    {                                                                 \
        _Pragma("unroll")                                             \
        for (int c = 0; c < 4; c++) {                                 \
            cpa16(&As[BUF][tid][c * 8], srcA0 + (K0) + c * 8);        \
            cpa16(&Bs[BUF][tid][c * 8], srcB0 + (K0) + c * 8);        \
        }                                                             \
    }

    QKV_ISSUE(0, 0); CPA_COMMIT;

    for (int it = 0; it < 16; it++) {
        CPA_WAIT0;
        __syncthreads();
        if (it + 1 < 16) { QKV_ISSUE((it + 1) * 32, (it + 1) & 1); CPA_COMMIT; }
        const int cb = it & 1;
#pragma unroll
        for (int kk = 0; kk < 32; kk += 16) {
            uint32_t a[4][4];
#pragma unroll
            for (int mi = 0; mi < 4; mi++)
#pragma unroll
                for (int p = 0; p < 4; p++)
                    a[mi][p] = *(const uint32_t*)&As[cb][wm * 64 + mi * 16 + ((p & 1) << 3) + g]
                                                   [kk + 2 * t + ((p >> 1) << 3)];
#pragma unroll
            for (int ni = 0; ni < 8; ni++) {
                uint32_t b0 = *(const uint32_t*)&Bs[cb][wn * 64 + ni * 8 + g][kk + 2 * t];
                uint32_t b1 = *(const uint32_t*)&Bs[cb][wn * 64 + ni * 8 + g][kk + 2 * t + 8];
#pragma unroll
                for (int mi = 0; mi < 4; mi++) mma16816(acc[mi][ni], a[mi], b0, b1);
            }
        }
        __syncthreads();
    }
#undef QKV_ISSUE

    const int mat = n0g >> 9, nloc = n0g & 511;
    const float* bias = (mat == 0) ? bq : (mat == 1) ? bk : bv;
    __nv_bfloat16* out = (mat == 0) ? g_Qh : (mat == 1) ? g_Kh : g_Vh;
    const float scale = (mat == 0) ? 0.125f : 1.0f;

#pragma unroll
    for (int mi = 0; mi < 4; mi++) {
        int r0 = m0 + wm * 64 + mi * 16 + g;
#pragma unroll
        for (int ni = 0; ni < 8; ni++) {
            int col = nloc + wn * 64 + ni * 8 + 2 * t;
            float b0f = bias[col], b1f = bias[col + 1];
            *(uint32_t*)(out + (size_t)r0 * 512 + col) =
                pack_bf16x2((acc[mi][ni][0] + b0f) * scale, (acc[mi][ni][1] + b1f) * scale);
            *(uint32_t*)(out + (size_t)(r0 + 8) * 512 + col) =
                pack_bf16x2((acc[mi][ni][2] + b0f) * scale, (acc[mi][ni][3] + b1f) * scale);
        }
    }
}

// ---------------- 2) pass1: row sums z[q] = sum_k exp(logit) (no store of S) ----
// grid (8, 8, 64): x = nblk, y = mblk, z = ss*32 + bh.
__global__ __launch_bounds__(128) void k_rowsum()
{
    __shared__ __nv_bfloat16 As[2][128][40];
    __shared__ __nv_bfloat16 Bs[2][128][40];
    __shared__ float zs[128][2];
    const int z = blockIdx.z;
    const int ss = z >> 5, bh = z & 31, b = bh >> 3, h = bh & 7;
    const __nv_bfloat16* Abase = g_Qh + ((size_t)(b * 2 + ss) * 1024) * 512 + h * 64;
    const __nv_bfloat16* Bbase = g_Kh + ((size_t)(b * 2 + (1 - ss)) * 1024) * 512 + h * 64;

    const int tid = threadIdx.x, lane = tid & 31, warp = tid >> 5;
    const int wm = warp >> 1, wn = warp & 1;
    const int g = lane >> 2, t = lane & 3;
    const int m0 = blockIdx.y * 128, n0 = blockIdx.x * 128;

    const __nv_bfloat16* srcA0 = Abase + (size_t)(m0 + tid) * 512;
    const __nv_bfloat16* srcB0 = Bbase + (size_t)(n0 + tid) * 512;

    float acc[4][8][4] = {};

#define SC_ISSUE(K0, BUF)                                             \
    {                                                                 \
        _Pragma("unroll")                                             \
        for (int c = 0; c < 4; c++) {                                 \
            cpa16(&As[BUF][tid][c * 8], srcA0 + (K0) + c * 8);        \
            cpa16(&Bs[BUF][tid][c * 8], srcB0 + (K0) + c * 8);        \
        }                                                             \
    }

    SC_ISSUE(0, 0); CPA_COMMIT;

    for (int it = 0; it < 2; it++) {
        CPA_WAIT0;
        __syncthreads();
        if (it + 1 < 2) { SC_ISSUE(32, 1); CPA_COMMIT; }
        const int cb = it & 1;
#pragma unroll
        for (int kk = 0; kk < 32; kk += 16) {
            uint32_t a[4][4];
#pragma unroll
            for (int mi = 0; mi < 4; mi++)
#pragma unroll
                for (int p = 0; p < 4; p++)
                    a[mi][p] = *(const uint32_t*)&As[cb][wm * 64 + mi * 16 + ((p & 1) << 3) + g]
                                                   [kk + 2 * t + ((p >> 1) << 3)];
#pragma unroll
            for (int ni = 0; ni < 8; ni++) {
                uint32_t b0 = *(const uint32_t*)&Bs[cb][wn * 64 + ni * 8 + g][kk + 2 * t];
                uint32_t b1 = *(const uint32_t*)&Bs[cb][wn * 64 + ni * 8 + g][kk + 2 * t + 8];
#pragma unroll
                for (int mi = 0; mi < 4; mi++) mma16816(acc[mi][ni], a[mi], b0, b1);
            }
        }
        __syncthreads();
    }
#undef SC_ISSUE

#pragma unroll
    for (int mi = 0; mi < 4; mi++) {
        float rs0 = 0.f, rs1 = 0.f;
#pragma unroll
        for (int ni = 0; ni < 8; ni++) {
            rs0 += __expf(acc[mi][ni][0]) + __expf(acc[mi][ni][1]);
            rs1 += __expf(acc[mi][ni][2]) + __expf(acc[mi][ni][3]);
        }
#pragma unroll
        for (int o = 1; o < 4; o <<= 1) {
            rs0 += __shfl_xor_sync(0xffffffffu, rs0, o);
            rs1 += __shfl_xor_sync(0xffffffffu, rs1, o);
        }
        if (t == 0) {
            zs[wm * 64 + mi * 16 + g][wn]     = rs0;
            zs[wm * 64 + mi * 16 + g + 8][wn] = rs1;
        }
    }
    __syncthreads();
    if (tid < 128) {
        float zsum = zs[tid][0] + zs[tid][1];
        g_zpart[((size_t)z * 8 + blockIdx.x) * 1024 + m0 + tid] = zsum;
    }
}

// ---------------- 3) fold partial sums -> reciprocal ----------------
__global__ __launch_bounds__(512) void k_zinv()
{
    const int i = blockIdx.x * 512 + threadIdx.x;
    const int z = i >> 10, q = i & 1023;
    float s = 0.f;
#pragma unroll
    for (int nb = 0; nb < 8; nb++) s += g_zpart[((size_t)z * 8 + nb) * 1024 + q];
    g_zinv[i] = __fdividef(1.f, s);
}

// ---------------- 4) pass2: recompute scores + normalize + compete + AV ----------
// grid (16, 32): x = 64-row q-tile, y = bh. 128 threads = 4 warps; warp w owns
// q-rows [w*16, w*16+16) of BOTH streams. Score C-fragments repack directly
// into AV A-fragments; S never touches memory.
__global__ __launch_bounds__(128) void k_attn_fused()
{
    __shared__ __nv_bfloat16 K1s[2][32][72];
    __shared__ __nv_bfloat16 K2s[2][32][72];
    __shared__ __nv_bfloat16 V1s[2][64][40];   // [dim][tok]
    __shared__ __nv_bfloat16 V2s[2][64][40];

    const int bh = blockIdx.y, b = bh >> 3, h = bh & 7;
    const int m0 = blockIdx.x * 64;
    const __nv_bfloat16* Q1 = g_Qh + ((size_t)(b * 2 + 0) * 1024) * 512 + h * 64;
    const __nv_bfloat16* Q2 = g_Qh + ((size_t)(b * 2 + 1) * 1024) * 512 + h * 64;
    const __nv_bfloat16* K1 = g_Kh + ((size_t)(b * 2 + 0) * 1024) * 512 + h * 64;
    const __nv_bfloat16* K2 = g_Kh + ((size_t)(b * 2 + 1) * 1024) * 512 + h * 64;
    const __nv_bfloat16* V1 = g_Vh + ((size_t)(b * 2 + 0) * 1024) * 512 + h * 64;
    const __nv_bfloat16* V2 = g_Vh + ((size_t)(b * 2 + 1) * 1024) * 512 + h * 64;
    __nv_bfloat16* C1 = g_attnh + ((size_t)(b * 2 + 0) * 1024) * 512 + h * 64;  // A12 @ V2
    __nv_bfloat16* C2 = g_attnh + ((size_t)(b * 2 + 1) * 1024) * 512 + h * 64;  // A21 @ V1

    const int tid = threadIdx.x, lane = tid & 31, warp = tid >> 5;
    const int g = lane >> 2, t = lane & 3;

    const float i1a = g_zinv[bh * 1024 + m0 + warp * 16 + g];
    const float i1b = g_zinv[bh * 1024 + m0 + warp * 16 + 8 + g];
    const float i2a = g_zinv[32768 + bh * 1024 + m0 + warp * 16 + g];
    const float i2b = g_zinv[32768 + bh * 1024 + m0 + warp * 16 + 8 + g];

    // Q A-fragments (held for the whole kernel). Stream1 logits use Q1 (vs K2),
    // stream2 logits use Q2 (vs K1). Same k-ascending chain as pass1.
    uint32_t qa1[4][4], qa2[4][4];
#pragma unroll
    for (int kc = 0; kc < 4; kc++)
#pragma unroll
        for (int p = 0; p < 4; p++) {
            const int row = m0 + warp * 16 + ((p & 1) << 3) + g;
            const int col = kc * 16 + ((p >> 1) << 3) + 2 * t;
            qa1[kc][p] = *(const uint32_t*)(Q1 + (size_t)row * 512 + col);
            qa2[kc][p] = *(const uint32_t*)(Q2 + (size_t)row * 512 + col);
        }

    // K/V tile load mappings: 32 rows (tokens) x 4 segments of 16 bf16
    const int krow = tid >> 2, kseg = (tid & 3) * 16;
    const __nv_bfloat16* srcK1 = K1 + (size_t)krow * 512 + kseg;
    const __nv_bfloat16* srcK2 = K2 + (size_t)krow * 512 + kseg;
    const __nv_bfloat16* srcV1 = V1 + (size_t)krow * 512 + kseg;
    const __nv_bfloat16* srcV2 = V2 + (size_t)krow * 512 + kseg;

    float o1[8][4] = {}, o2[8][4] = {};
    __nv_bfloat16 vr1[16], vr2[16];

#define ATT_ISSUE_K(K0, BUF)                                          \
    {                                                                 \
        cpa16(&K1s[BUF][krow][kseg],     srcK1 + (size_t)(K0) * 512); \
        cpa16(&K1s[BUF][krow][kseg + 8], srcK1 + (size_t)(K0) * 512 + 8); \
        cpa16(&K2s[BUF][krow][kseg],     srcK2 + (size_t)(K0) * 512); \
        cpa16(&K2s[BUF][krow][kseg + 8], srcK2 + (size_t)(K0) * 512 + 8); \
    }
#define ATT_LD_V(K0)                                                  \
    {                                                                 \
        const __nv_bfloat16* s1 = srcV1 + (size_t)(K0) * 512;         \
        const __nv_bfloat16* s2 = srcV2 + (size_t)(K0) * 512;         \
        *(uint4*)vr1       = *(const uint4*)s1;                       \
        *(uint4*)(vr1 + 8) = *(const uint4*)(s1 + 8);                 \
        *(uint4*)vr2       = *(const uint4*)s2;                       \
        *(uint4*)(vr2 + 8) = *(const uint4*)(s2 + 8);                 \
    }
#define ATT_ST_V(BUF)                                                 \
    {                                                                 \
        _Pragma("unroll")                                             \
        for (int j = 0; j < 16; j++) {                                \
            V1s[BUF][kseg + j][krow] = vr1[j];                        \
            V2s[BUF][kseg + j][krow] = vr2[j];                        \
        }                                                             \
    }

    ATT_ISSUE_K(0, 0); CPA_COMMIT;
    ATT_LD_V(0); ATT_ST_V(0);
    ATT_LD_V(32);

    for (int it = 0; it < 32; it++) {
        CPA_WAIT0;
        __syncthreads();
        if (it + 1 < 32) { ATT_ISSUE_K((it + 1) * 32, (it + 1) & 1); CPA_COMMIT; }
        const int cb = it & 1;

        // ---- score fragments for this 32-token tile (both streams) ----
        uint32_t na1[2][4], na2[2][4];   // AV A-frags [kc2][p]
#pragma unroll
        for (int nb = 0; nb < 4; nb++) {
            float c12[4] = {}, c21[4] = {};
#pragma unroll
            for (int kc = 0; kc < 4; kc++) {
                uint32_t b0 = *(const uint32_t*)&K2s[cb][nb * 8 + g][kc * 16 + 2 * t];
                uint32_t b1 = *(const uint32_t*)&K2s[cb][nb * 8 + g][kc * 16 + 2 * t + 8];
                mma16816(c12, qa1[kc], b0, b1);
                uint32_t d0 = *(const uint32_t*)&K1s[cb][nb * 8 + g][kc * 16 + 2 * t];
                uint32_t d1 = *(const uint32_t*)&K1s[cb][nb * 8 + g][kc * 16 + 2 * t + 8];
                mma16816(c21, qa2[kc], d0, d1);
            }
            // exp + normalize + compete (rows g use *a, rows g+8 use *b)
            float s10 = __expf(c12[0]) * i1a, s11 = __expf(c12[1]) * i1a;
            float s12f = __expf(c12[2]) * i1b, s13 = __expf(c12[3]) * i1b;
            float s20 = __expf(c21[0]) * i2a, s21f = __expf(c21[1]) * i2a;
            float s22 = __expf(c21[2]) * i2b, s23 = __expf(c21[3]) * i2b;
            float d0 = s10 + s20 + 1e-6f, d1 = s11 + s21f + 1e-6f;
            float d2 = s12f + s22 + 1e-6f, d3 = s13 + s23 + 1e-6f;
            float ra = rcp_approx(d0 * d1);
            float rb = rcp_approx(d2 * d3);
            float inv0 = ra * d1, inv1 = ra * d0;
            float inv2 = rb * d3, inv3 = rb * d2;
            const int kc2 = nb >> 1, pb = (nb & 1) << 1;
            na1[kc2][pb]     = pack_bf16x2(s10 * inv0, s11 * inv1);
            na1[kc2][pb + 1] = pack_bf16x2(s12f * inv2, s13 * inv3);
            na2[kc2][pb]     = pack_bf16x2(s20 * inv0, s21f * inv1);
            na2[kc2][pb + 1] = pack_bf16x2(s22 * inv2, s23 * inv3);
        }

        // ---- AV mmas (k = 32 tokens = 2 chunks) ----
#pragma unroll
        for (int nd = 0; nd < 8; nd++) {
            const int cbase = nd * 8 + g;
#pragma unroll
            for (int kc2 = 0; kc2 < 2; kc2++) {
                uint32_t b20 = *(const uint32_t*)&V2s[cb][cbase][kc2 * 16 + 2 * t];
                uint32_t b21 = *(const uint32_t*)&V2s[cb][cbase][kc2 * 16 + 2 * t + 8];
                mma16816(o1[nd], na1[kc2], b20, b21);
                uint32_t b10 = *(const uint32_t*)&V1s[cb][cbase][kc2 * 16 + 2 * t];
                uint32_t b11 = *(const uint32_t*)&V1s[cb][cbase][kc2 * 16 + 2 * t + 8];
                mma16816(o2[nd], na2[kc2], b10, b11);
            }
        }

        if (it + 1 < 32) {
            ATT_ST_V((it + 1) & 1);
            if (it + 2 < 32) ATT_LD_V((it + 2) * 32);
        }
    }
#undef ATT_ISSUE_K
#undef ATT_LD_V
#undef ATT_ST_V

    const int r0 = m0 + warp * 16 + g;
#pragma unroll
    for (int nd = 0; nd < 8; nd++) {
        int col = nd * 8 + 2 * t;
        *(uint32_t*)(C1 + (size_t)r0 * 512 + col)       = pack_bf16x2(o1[nd][0], o1[nd][1]);
        *(uint32_t*)(C1 + (size_t)(r0 + 8) * 512 + col) = pack_bf16x2(o1[nd][2], o1[nd][3]);
        *(uint32_t*)(C2 + (size_t)r0 * 512 + col)       = pack_bf16x2(o2[nd][0], o2[nd][1]);
        *(uint32_t*)(C2 + (size_t)(r0 + 8) * 512 + col) = pack_bf16x2(o2[nd][2], o2[nd][3]);
    }
}

// ---------------- 5) output projection: g_proj = attn @ Wo^T + bo ----------------
__global__ __launch_bounds__(128) void k_out_mma(const float* __restrict__ bo)
{
    __shared__ __nv_bfloat16 As[2][128][40];
    __shared__ __nv_bfloat16 Bs[2][128][40];
    const int tid = threadIdx.x, lane = tid & 31, warp = tid >> 5;
    const int wm = warp >> 1, wn = warp & 1;
    const int g = lane >> 2, t = lane & 3;
    const int m0 = blockIdx.y * 128, n0 = blockIdx.x * 128;
    const __nv_bfloat16* Wo = g_Wh + 3ull * 512 * 512;

    const __nv_bfloat16* srcA0 = g_attnh + (size_t)(m0 + tid) * 512;
    const __nv_bfloat16* srcB0 = Wo + (size_t)(n0 + tid) * 512;

    float acc[4][8][4] = {};

#define OUT_ISSUE(K0, BUF)                                            \
    {                                                                 \
        _Pragma("unroll")                                             \
        for (int c = 0; c < 4; c++) {                                 \
            cpa16(&As[BUF][tid][c * 8], srcA0 + (K0) + c * 8);        \
            cpa16(&Bs[BUF][tid][c * 8], srcB0 + (K0) + c * 8);        \
        }                                                             \
    }

    OUT_ISSUE(0, 0); CPA_COMMIT;

    for (int it = 0; it < 16; it++) {
        CPA_WAIT0;
        __syncthreads();
        if (it + 1 < 16) { OUT_ISSUE((it + 1) * 32, (it + 1) & 1); CPA_COMMIT; }
        const int cb = it & 1;
#pragma unroll
        for (int kk = 0; kk < 32; kk += 16) {
            uint32_t a[4][4];
#pragma unroll
            for (int mi = 0; mi < 4; mi++)
#pragma unroll
                for (int p = 0; p < 4; p++)
                    a[mi][p] = *(const uint32_t*)&As[cb][wm * 64 + mi * 16 + ((p & 1) << 3) + g]
                                                   [kk + 2 * t + ((p >> 1) << 3)];
#pragma unroll
            for (int ni = 0; ni < 8; ni++) {
                uint32_t b0 = *(const uint32_t*)&Bs[cb][wn * 64 + ni * 8 + g][kk + 2 * t];
                uint32_t b1 = *(const uint32_t*)&Bs[cb][wn * 64 + ni * 8 + g][kk + 2 * t + 8];
#pragma unroll
                for (int mi = 0; mi < 4; mi++) mma16816(acc[mi][ni], a[mi], b0, b1);
            }
        }
        __syncthreads();
    }
#undef OUT_ISSUE

#pragma unroll
    for (int mi = 0; mi < 4; mi++) {
        int r0 = m0 + wm * 64 + mi * 16 + g;
#pragma unroll
        for (int ni = 0; ni < 8; ni++) {
            int col = n0 + wn * 64 + ni * 8 + 2 * t;
            float b0f = bo[col], b1f = bo[col + 1];
            *(float2*)(g_proj + (size_t)r0 * 512 + col) =
                make_float2(acc[mi][ni][0] + b0f, acc[mi][ni][1] + b1f);
            *(float2*)(g_proj + (size_t)(r0 + 8) * 512 + col) =
                make_float2(acc[mi][ni][2] + b0f, acc[mi][ni][3] + b1f);
        }
    }
}

// ---------------- 6) LayerNorm + gate + residual ----------------
__global__ __launch_bounds__(256) void k_ln(
    const float* __restrict__ hidden,
    const float* __restrict__ ln_g, const float* __restrict__ ln_b,
    const float* __restrict__ alpha, float* __restrict__ out)
{
    const int m = blockIdx.x;
    const int s = (m >> 10) & 1;
    const float* p = g_proj + (size_t)m * 512;
    const int tid = threadIdx.x;
    __shared__ float sm[8];

    float x0 = p[tid], x1 = p[tid + 256];
    float sum = blk_red_sum(x0 + x1, sm);
    float sq  = blk_red_sum(x0 * x0 + x1 * x1, sm);
    float mu  = sum * (1.f / 512.f);
    float var = sq * (1.f / 512.f) - mu * mu;
    float rstd = rsqrtf(var + 1e-5f);
    float al = alpha[s];
    size_t base = (size_t)m * 512;

    {
        int e = tid;
        float y = (x0 - mu) * rstd * ln_g[s * 512 + e] + ln_b[s * 512 + e];
        out[base + e] = hidden[base + e] + y * al;
    }
    {
        int e = tid + 256;
        float y = (x1 - mu) * rstd * ln_g[s * 512 + e] + ln_b[s * 512 + e];
        out[base + e] = hidden[base + e] + y * al;
    }
}

// ---------------- launch ----------------
extern "C" void kernel_launch(void* const* d_in, const int* in_sizes, int n_in,
                              void* d_out, int out_size)
{
    const float* hidden = (const float*)d_in[0];
    const float* Wq = (const float*)d_in[1];  const float* bq = (const float*)d_in[2];
    const float* Wk = (const float*)d_in[3];  const float* bk = (const float*)d_in[4];
    const float* Wv = (const float*)d_in[5];  const float* bv = (const float*)d_in[6];
    const float* Wo = (const float*)d_in[7];  const float* bo = (const float*)d_in[8];
    const float* lng = (const float*)d_in[9]; const float* lnb = (const float*)d_in[10];
    const float* alpha = (const float*)d_in[11];
    float* out = (float*)d_out;

    k_prep<<<5120, 256>>>(hidden, Wq, Wk, Wv, Wo);
    k_qkv_mma<<<dim3(12, 64), 128>>>(bq, bk, bv);
    k_rowsum<<<dim3(8, 8, 64), 128>>>();
    k_zinv<<<128, 512>>>();
    k_attn_fused<<<dim3(16, 32), 128>>>();
    k_out_mma<<<dim3(4, 64), 128>>>(bo);
    k_ln<<<8192, 256>>>(hidden, lng, lnb, alpha, out);
}

// round 13
// speedup vs baseline: 1.6550x; 1.0707x over previous
#include <cuda_runtime.h>
#include <cuda_bf16.h>
#include <stdint.h>
#include <math.h>

// Shapes (fixed): B=4, S=2, T=1024, D=512, H=8, HD=64, M = B*S*T = 8192
// bf16 tensor-core GEMMs (mma.sync m16n8k16, fp32 accum), 2-stage cp.async.
// Single fused attention kernel: loop1 computes z (rowsums of exp) locally in
// registers, loop2 recomputes score fragments, normalizes + competitive-
// combines on the C->A repack, and runs AV. Q carries 0.125*log2(e) so exp
// is a bare ex2.approx. No score matrix, no z workspace, 5 launches total.

// ---------------- device workspaces ----------------
__device__ __nv_bfloat16 g_Xh[8192ull * 512];
__device__ __nv_bfloat16 g_Wh[4ull * 512 * 512];  // [Wq;Wk;Wv;Wo]
__device__ __nv_bfloat16 g_Qh[8192ull * 512];     // Q * 0.125 * log2(e)
__device__ __nv_bfloat16 g_Kh[8192ull * 512];
__device__ __nv_bfloat16 g_Vh[8192ull * 512];
__device__ __nv_bfloat16 g_attnh[8192ull * 512];
__device__ float         g_proj[8192ull * 512];

// ---------------- helpers ----------------
__device__ __forceinline__ uint32_t pack_bf16x2(float a, float b) {
    __nv_bfloat162 h = __floats2bfloat162_rn(a, b);
    return *reinterpret_cast<uint32_t*>(&h);
}

__device__ __forceinline__ void mma16816(float* c, const uint32_t* a, uint32_t b0, uint32_t b1) {
    asm volatile(
        "mma.sync.aligned.m16n8k16.row.col.f32.bf16.bf16.f32 "
        "{%0,%1,%2,%3}, {%4,%5,%6,%7}, {%8,%9}, {%0,%1,%2,%3};\n"
        : "+f"(c[0]), "+f"(c[1]), "+f"(c[2]), "+f"(c[3])
        : "r"(a[0]), "r"(a[1]), "r"(a[2]), "r"(a[3]), "r"(b0), "r"(b1));
}

__device__ __forceinline__ void cpa16(void* smem, const void* g) {
    uint32_t s = (uint32_t)__cvta_generic_to_shared(smem);
    asm volatile("cp.async.cg.shared.global [%0], [%1], 16;" :: "r"(s), "l"(g));
}
#define CPA_COMMIT asm volatile("cp.async.commit_group;")
#define CPA_WAIT0  asm volatile("cp.async.wait_group 0;")

__device__ __forceinline__ float rcp_approx(float x) {
    float r;
    asm("rcp.approx.f32 %0, %1;" : "=f"(r) : "f"(x));
    return r;
}

__device__ __forceinline__ float ex2f(float x) {
    float r;
    asm("ex2.approx.f32 %0, %1;" : "=f"(r) : "f"(x));
    return r;
}

__device__ __forceinline__ float blk_red_sum(float v, float* sm) {
    int lane = threadIdx.x & 31, wid = threadIdx.x >> 5;
#pragma unroll
    for (int o = 16; o; o >>= 1) v += __shfl_xor_sync(0xffffffffu, v, o);
    if (lane == 0) sm[wid] = v;
    __syncthreads();
    float r = 0.f;
#pragma unroll
    for (int i = 0; i < 8; i++) r += sm[i];
    __syncthreads();
    return r;
}

// ---------------- 0) convert inputs to bf16 ----------------
__global__ __launch_bounds__(256) void k_prep(
    const float* __restrict__ X,
    const float* __restrict__ Wq, const float* __restrict__ Wk,
    const float* __restrict__ Wv, const float* __restrict__ Wo)
{
    const int idx = blockIdx.x * 256 + threadIdx.x;
    if (idx < 1048576) {
        float4 v = ((const float4*)X)[idx];
        uint2 o; o.x = pack_bf16x2(v.x, v.y); o.y = pack_bf16x2(v.z, v.w);
        ((uint2*)g_Xh)[idx] = o;
    } else {
        int j = idx - 1048576;
        int w = j >> 16;
        const float4* src = (w == 0) ? (const float4*)Wq : (w == 1) ? (const float4*)Wk
                          : (w == 2) ? (const float4*)Wv : (const float4*)Wo;
        float4 v = src[j & 65535];
        uint2 o; o.x = pack_bf16x2(v.x, v.y); o.y = pack_bf16x2(v.z, v.w);
        ((uint2*)g_Wh)[j] = o;
    }
}

// ---------------- 1) QKV projection (bf16 mma, cp.async 2-stage) ----------------
__global__ __launch_bounds__(128) void k_qkv_mma(
    const float* __restrict__ bq, const float* __restrict__ bk, const float* __restrict__ bv)
{
    __shared__ __nv_bfloat16 As[2][128][40];
    __shared__ __nv_bfloat16 Bs[2][128][40];
    const int tid = threadIdx.x, lane = tid & 31, warp = tid >> 5;
    const int wm = warp >> 1, wn = warp & 1;
    const int g = lane >> 2, t = lane & 3;
    const int m0 = blockIdx.y * 128, n0g = blockIdx.x * 128;

    const __nv_bfloat16* srcA0 = g_Xh + (size_t)(m0 + tid) * 512;
    const __nv_bfloat16* srcB0 = g_Wh + (size_t)(n0g + tid) * 512;

    float acc[4][8][4] = {};

#define QKV_ISSUE(K0, BUF)                                            \
    {                                                                 \
        _Pragma("unroll")                                             \
        for (int c = 0; c < 4; c++) {                                 \
            cpa16(&As[BUF][tid][c * 8], srcA0 + (K0) + c * 8);        \
            cpa16(&Bs[BUF][tid][c * 8], srcB0 + (K0) + c * 8);        \
        }                                                             \
    }

    QKV_ISSUE(0, 0); CPA_COMMIT;

    for (int it = 0; it < 16; it++) {
        CPA_WAIT0;
        __syncthreads();
        if (it + 1 < 16) { QKV_ISSUE((it + 1) * 32, (it + 1) & 1); CPA_COMMIT; }
        const int cb = it & 1;
#pragma unroll
        for (int kk = 0; kk < 32; kk += 16) {
            uint32_t a[4][4];
#pragma unroll
            for (int mi = 0; mi < 4; mi++)
#pragma unroll
                for (int p = 0; p < 4; p++)
                    a[mi][p] = *(const uint32_t*)&As[cb][wm * 64 + mi * 16 + ((p & 1) << 3) + g]
                                                   [kk + 2 * t + ((p >> 1) << 3)];
#pragma unroll
            for (int ni = 0; ni < 8; ni++) {
                uint32_t b0 = *(const uint32_t*)&Bs[cb][wn * 64 + ni * 8 + g][kk + 2 * t];
                uint32_t b1 = *(const uint32_t*)&Bs[cb][wn * 64 + ni * 8 + g][kk + 2 * t + 8];
#pragma unroll
                for (int mi = 0; mi < 4; mi++) mma16816(acc[mi][ni], a[mi], b0, b1);
            }
        }
        __syncthreads();
    }
#undef QKV_ISSUE

    const int mat = n0g >> 9, nloc = n0g & 511;
    const float* bias = (mat == 0) ? bq : (mat == 1) ? bk : bv;
    __nv_bfloat16* out = (mat == 0) ? g_Qh : (mat == 1) ? g_Kh : g_Vh;
    // Q scale: 1/sqrt(64) * log2(e) so attention logits are base-2 ready.
    const float scale = (mat == 0) ? 0.125f * 1.4426950408889634f : 1.0f;

#pragma unroll
    for (int mi = 0; mi < 4; mi++) {
        int r0 = m0 + wm * 64 + mi * 16 + g;
#pragma unroll
        for (int ni = 0; ni < 8; ni++) {
            int col = nloc + wn * 64 + ni * 8 + 2 * t;
            float b0f = bias[col], b1f = bias[col + 1];
            *(uint32_t*)(out + (size_t)r0 * 512 + col) =
                pack_bf16x2((acc[mi][ni][0] + b0f) * scale, (acc[mi][ni][1] + b1f) * scale);
            *(uint32_t*)(out + (size_t)(r0 + 8) * 512 + col) =
                pack_bf16x2((acc[mi][ni][2] + b0f) * scale, (acc[mi][ni][3] + b1f) * scale);
        }
    }
}

// ---------------- 2) fused attention: rowsum pass + normalize+compete+AV ------
// grid (16, 32): x = 64-row q-tile, y = bh. 128 threads = 4 warps; warp w owns
// q-rows [w*16, w*16+16) of BOTH streams. z computed locally (loop1), S never
// touches memory, identical mma chains in both loops => bit-consistent logits.
__global__ __launch_bounds__(128) void k_attn_fused()
{
    __shared__ __nv_bfloat16 K1s[2][32][72];
    __shared__ __nv_bfloat16 K2s[2][32][72];
    __shared__ __nv_bfloat16 V1s[2][64][40];   // [dim][tok]
    __shared__ __nv_bfloat16 V2s[2][64][40];

    const int bh = blockIdx.y, b = bh >> 3, h = bh & 7;
    const int m0 = blockIdx.x * 64;
    const __nv_bfloat16* Q1 = g_Qh + ((size_t)(b * 2 + 0) * 1024) * 512 + h * 64;
    const __nv_bfloat16* Q2 = g_Qh + ((size_t)(b * 2 + 1) * 1024) * 512 + h * 64;
    const __nv_bfloat16* K1 = g_Kh + ((size_t)(b * 2 + 0) * 1024) * 512 + h * 64;
    const __nv_bfloat16* K2 = g_Kh + ((size_t)(b * 2 + 1) * 1024) * 512 + h * 64;
    const __nv_bfloat16* V1 = g_Vh + ((size_t)(b * 2 + 0) * 1024) * 512 + h * 64;
    const __nv_bfloat16* V2 = g_Vh + ((size_t)(b * 2 + 1) * 1024) * 512 + h * 64;
    __nv_bfloat16* C1 = g_attnh + ((size_t)(b * 2 + 0) * 1024) * 512 + h * 64;  // A12 @ V2
    __nv_bfloat16* C2 = g_attnh + ((size_t)(b * 2 + 1) * 1024) * 512 + h * 64;  // A21 @ V1

    const int tid = threadIdx.x, lane = tid & 31, warp = tid >> 5;
    const int g = lane >> 2, t = lane & 3;

    // Q A-fragments, held in registers for the whole kernel.
    uint32_t qa1[4][4], qa2[4][4];
#pragma unroll
    for (int kc = 0; kc < 4; kc++)
#pragma unroll
        for (int p = 0; p < 4; p++) {
            const int row = m0 + warp * 16 + ((p & 1) << 3) + g;
            const int col = kc * 16 + ((p >> 1) << 3) + 2 * t;
            qa1[kc][p] = *(const uint32_t*)(Q1 + (size_t)row * 512 + col);
            qa2[kc][p] = *(const uint32_t*)(Q2 + (size_t)row * 512 + col);
        }

    // K/V tile load mappings: 32 rows (tokens) x 4 segments of 16 bf16
    const int krow = tid >> 2, kseg = (tid & 3) * 16;
    const __nv_bfloat16* srcK1 = K1 + (size_t)krow * 512 + kseg;
    const __nv_bfloat16* srcK2 = K2 + (size_t)krow * 512 + kseg;
    const __nv_bfloat16* srcV1 = V1 + (size_t)krow * 512 + kseg;
    const __nv_bfloat16* srcV2 = V2 + (size_t)krow * 512 + kseg;

#define ATT_ISSUE_K(K0, BUF)                                              \
    {                                                                     \
        cpa16(&K1s[BUF][krow][kseg],     srcK1 + (size_t)(K0) * 512);     \
        cpa16(&K1s[BUF][krow][kseg + 8], srcK1 + (size_t)(K0) * 512 + 8); \
        cpa16(&K2s[BUF][krow][kseg],     srcK2 + (size_t)(K0) * 512);     \
        cpa16(&K2s[BUF][krow][kseg + 8], srcK2 + (size_t)(K0) * 512 + 8); \
    }

    // ================= loop 1: row sums z (K only) =================
    float z1a = 0.f, z1b = 0.f, z2a = 0.f, z2b = 0.f;

    ATT_ISSUE_K(0, 0); CPA_COMMIT;
    for (int it = 0; it < 32; it++) {
        CPA_WAIT0;
        __syncthreads();
        if (it + 1 < 32) { ATT_ISSUE_K((it + 1) * 32, (it + 1) & 1); CPA_COMMIT; }
        const int cb = it & 1;
#pragma unroll
        for (int nb = 0; nb < 4; nb++) {
            float c12[4] = {}, c21[4] = {};
#pragma unroll
            for (int kc = 0; kc < 4; kc++) {
                uint32_t b0 = *(const uint32_t*)&K2s[cb][nb * 8 + g][kc * 16 + 2 * t];
                uint32_t b1 = *(const uint32_t*)&K2s[cb][nb * 8 + g][kc * 16 + 2 * t + 8];
                mma16816(c12, qa1[kc], b0, b1);
                uint32_t d0 = *(const uint32_t*)&K1s[cb][nb * 8 + g][kc * 16 + 2 * t];
                uint32_t d1 = *(const uint32_t*)&K1s[cb][nb * 8 + g][kc * 16 + 2 * t + 8];
                mma16816(c21, qa2[kc], d0, d1);
            }
            z1a += ex2f(c12[0]) + ex2f(c12[1]);
            z1b += ex2f(c12[2]) + ex2f(c12[3]);
            z2a += ex2f(c21[0]) + ex2f(c21[1]);
            z2b += ex2f(c21[2]) + ex2f(c21[3]);
        }
        __syncthreads();
    }
    // reduce over the 4 t-lanes of each quad (lane = g*4 + t)
#pragma unroll
    for (int o = 1; o < 4; o <<= 1) {
        z1a += __shfl_xor_sync(0xffffffffu, z1a, o);
        z1b += __shfl_xor_sync(0xffffffffu, z1b, o);
        z2a += __shfl_xor_sync(0xffffffffu, z2a, o);
        z2b += __shfl_xor_sync(0xffffffffu, z2b, o);
    }
    const float i1a = __fdividef(1.f, z1a), i1b = __fdividef(1.f, z1b);
    const float i2a = __fdividef(1.f, z2a), i2b = __fdividef(1.f, z2b);

    // ================= loop 2: normalize + compete + AV =================
    float o1[8][4] = {}, o2[8][4] = {};
    __nv_bfloat16 vr1[16], vr2[16];

#define ATT_LD_V(K0)                                                  \
    {                                                                 \
        const __nv_bfloat16* s1 = srcV1 + (size_t)(K0) * 512;         \
        const __nv_bfloat16* s2 = srcV2 + (size_t)(K0) * 512;         \
        *(uint4*)vr1       = *(const uint4*)s1;                       \
        *(uint4*)(vr1 + 8) = *(const uint4*)(s1 + 8);                 \
        *(uint4*)vr2       = *(const uint4*)s2;                       \
        *(uint4*)(vr2 + 8) = *(const uint4*)(s2 + 8);                 \
    }
#define ATT_ST_V(BUF)                                                 \
    {                                                                 \
        _Pragma("unroll")                                             \
        for (int j = 0; j < 16; j++) {                                \
            V1s[BUF][kseg + j][krow] = vr1[j];                        \
            V2s[BUF][kseg + j][krow] = vr2[j];                        \
        }                                                             \
    }

    ATT_ISSUE_K(0, 0); CPA_COMMIT;
    ATT_LD_V(0); ATT_ST_V(0);
    ATT_LD_V(32);

    for (int it = 0; it < 32; it++) {
        CPA_WAIT0;
        __syncthreads();
        if (it + 1 < 32) { ATT_ISSUE_K((it + 1) * 32, (it + 1) & 1); CPA_COMMIT; }
        const int cb = it & 1;

        uint32_t na1[2][4], na2[2][4];   // AV A-frags [kc2][p]
#pragma unroll
        for (int nb = 0; nb < 4; nb++) {
            float c12[4] = {}, c21[4] = {};
#pragma unroll
            for (int kc = 0; kc < 4; kc++) {
                uint32_t b0 = *(const uint32_t*)&K2s[cb][nb * 8 + g][kc * 16 + 2 * t];
                uint32_t b1 = *(const uint32_t*)&K2s[cb][nb * 8 + g][kc * 16 + 2 * t + 8];
                mma16816(c12, qa1[kc], b0, b1);
                uint32_t d0 = *(const uint32_t*)&K1s[cb][nb * 8 + g][kc * 16 + 2 * t];
                uint32_t d1 = *(const uint32_t*)&K1s[cb][nb * 8 + g][kc * 16 + 2 * t + 8];
                mma16816(c21, qa2[kc], d0, d1);
            }
            float s10 = ex2f(c12[0]) * i1a, s11 = ex2f(c12[1]) * i1a;
            float s12f = ex2f(c12[2]) * i1b, s13 = ex2f(c12[3]) * i1b;
            float s20 = ex2f(c21[0]) * i2a, s21f = ex2f(c21[1]) * i2a;
            float s22 = ex2f(c21[2]) * i2b, s23 = ex2f(c21[3]) * i2b;
            float d0 = s10 + s20 + 1e-6f, d1 = s11 + s21f + 1e-6f;
            float d2 = s12f + s22 + 1e-6f, d3 = s13 + s23 + 1e-6f;
            float ra = rcp_approx(d0 * d1);
            float rb = rcp_approx(d2 * d3);
            float inv0 = ra * d1, inv1 = ra * d0;
            float inv2 = rb * d3, inv3 = rb * d2;
            const int kc2 = nb >> 1, pb = (nb & 1) << 1;
            na1[kc2][pb]     = pack_bf16x2(s10 * inv0, s11 * inv1);
            na1[kc2][pb + 1] = pack_bf16x2(s12f * inv2, s13 * inv3);
            na2[kc2][pb]     = pack_bf16x2(s20 * inv0, s21f * inv1);
            na2[kc2][pb + 1] = pack_bf16x2(s22 * inv2, s23 * inv3);
        }

#pragma unroll
        for (int nd = 0; nd < 8; nd++) {
            const int cbase = nd * 8 + g;
#pragma unroll
            for (int kc2 = 0; kc2 < 2; kc2++) {
                uint32_t b20 = *(const uint32_t*)&V2s[cb][cbase][kc2 * 16 + 2 * t];
                uint32_t b21 = *(const uint32_t*)&V2s[cb][cbase][kc2 * 16 + 2 * t + 8];
                mma16816(o1[nd], na1[kc2], b20, b21);
                uint32_t b10 = *(const uint32_t*)&V1s[cb][cbase][kc2 * 16 + 2 * t];
                uint32_t b11 = *(const uint32_t*)&V1s[cb][cbase][kc2 * 16 + 2 * t + 8];
                mma16816(o2[nd], na2[kc2], b10, b11);
            }
        }

        if (it + 1 < 32) {
            ATT_ST_V((it + 1) & 1);
            if (it + 2 < 32) ATT_LD_V((it + 2) * 32);
        }
    }
#undef ATT_ISSUE_K
#undef ATT_LD_V
#undef ATT_ST_V

    const int r0 = m0 + warp * 16 + g;
#pragma unroll
    for (int nd = 0; nd < 8; nd++) {
        int col = nd * 8 + 2 * t;
        *(uint32_t*)(C1 + (size_t)r0 * 512 + col)       = pack_bf16x2(o1[nd][0], o1[nd][1]);
        *(uint32_t*)(C1 + (size_t)(r0 + 8) * 512 + col) = pack_bf16x2(o1[nd][2], o1[nd][3]);
        *(uint32_t*)(C2 + (size_t)r0 * 512 + col)       = pack_bf16x2(o2[nd][0], o2[nd][1]);
        *(uint32_t*)(C2 + (size_t)(r0 + 8) * 512 + col) = pack_bf16x2(o2[nd][2], o2[nd][3]);
    }
}

// ---------------- 3) output projection: g_proj = attn @ Wo^T + bo ----------------
__global__ __launch_bounds__(128) void k_out_mma(const float* __restrict__ bo)
{
    __shared__ __nv_bfloat16 As[2][128][40];
    __shared__ __nv_bfloat16 Bs[2][128][40];
    const int tid = threadIdx.x, lane = tid & 31, warp = tid >> 5;
    const int wm = warp >> 1, wn = warp & 1;
    const int g = lane >> 2, t = lane & 3;
    const int m0 = blockIdx.y * 128, n0 = blockIdx.x * 128;
    const __nv_bfloat16* Wo = g_Wh + 3ull * 512 * 512;

    const __nv_bfloat16* srcA0 = g_attnh + (size_t)(m0 + tid) * 512;
    const __nv_bfloat16* srcB0 = Wo + (size_t)(n0 + tid) * 512;

    float acc[4][8][4] = {};

#define OUT_ISSUE(K0, BUF)                                            \
    {                                                                 \
        _Pragma("unroll")                                             \
        for (int c = 0; c < 4; c++) {                                 \
            cpa16(&As[BUF][tid][c * 8], srcA0 + (K0) + c * 8);        \
            cpa16(&Bs[BUF][tid][c * 8], srcB0 + (K0) + c * 8);        \
        }                                                             \
    }

    OUT_ISSUE(0, 0); CPA_COMMIT;

    for (int it = 0; it < 16; it++) {
        CPA_WAIT0;
        __syncthreads();
        if (it + 1 < 16) { OUT_ISSUE((it + 1) * 32, (it + 1) & 1); CPA_COMMIT; }
        const int cb = it & 1;
#pragma unroll
        for (int kk = 0; kk < 32; kk += 16) {
            uint32_t a[4][4];
#pragma unroll
            for (int mi = 0; mi < 4; mi++)
#pragma unroll
                for (int p = 0; p < 4; p++)
                    a[mi][p] = *(const uint32_t*)&As[cb][wm * 64 + mi * 16 + ((p & 1) << 3) + g]
                                                   [kk + 2 * t + ((p >> 1) << 3)];
#pragma unroll
            for (int ni = 0; ni < 8; ni++) {
                uint32_t b0 = *(const uint32_t*)&Bs[cb][wn * 64 + ni * 8 + g][kk + 2 * t];
                uint32_t b1 = *(const uint32_t*)&Bs[cb][wn * 64 + ni * 8 + g][kk + 2 * t + 8];
#pragma unroll
                for (int mi = 0; mi < 4; mi++) mma16816(acc[mi][ni], a[mi], b0, b1);
            }
        }
        __syncthreads();
    }
#undef OUT_ISSUE

#pragma unroll
    for (int mi = 0; mi < 4; mi++) {
        int r0 = m0 + wm * 64 + mi * 16 + g;
#pragma unroll
        for (int ni = 0; ni < 8; ni++) {
            int col = n0 + wn * 64 + ni * 8 + 2 * t;
            float b0f = bo[col], b1f = bo[col + 1];
            *(float2*)(g_proj + (size_t)r0 * 512 + col) =
                make_float2(acc[mi][ni][0] + b0f, acc[mi][ni][1] + b1f);
            *(float2*)(g_proj + (size_t)(r0 + 8) * 512 + col) =
                make_float2(acc[mi][ni][2] + b0f, acc[mi][ni][3] + b1f);
        }
    }
}

// ---------------- 4) LayerNorm + gate + residual ----------------
__global__ __launch_bounds__(256) void k_ln(
    const float* __restrict__ hidden,
    const float* __restrict__ ln_g, const float* __restrict__ ln_b,
    const float* __restrict__ alpha, float* __restrict__ out)
{
    const int m = blockIdx.x;
    const int s = (m >> 10) & 1;
    const float* p = g_proj + (size_t)m * 512;
    const int tid = threadIdx.x;
    __shared__ float sm[8];

    float x0 = p[tid], x1 = p[tid + 256];
    float sum = blk_red_sum(x0 + x1, sm);
    float sq  = blk_red_sum(x0 * x0 + x1 * x1, sm);
    float mu  = sum * (1.f / 512.f);
    float var = sq * (1.f / 512.f) - mu * mu;
    float rstd = rsqrtf(var + 1e-5f);
    float al = alpha[s];
    size_t base = (size_t)m * 512;

    {
        int e = tid;
        float y = (x0 - mu) * rstd * ln_g[s * 512 + e] + ln_b[s * 512 + e];
        out[base + e] = hidden[base + e] + y * al;
    }
    {
        int e = tid + 256;
        float y = (x1 - mu) * rstd * ln_g[s * 512 + e] + ln_b[s * 512 + e];
        out[base + e] = hidden[base + e] + y * al;
    }
}

// ---------------- launch ----------------
extern "C" void kernel_launch(void* const* d_in, const int* in_sizes, int n_in,
                              void* d_out, int out_size)
{
    const float* hidden = (const float*)d_in[0];
    const float* Wq = (const float*)d_in[1];  const float* bq = (const float*)d_in[2];
    const float* Wk = (const float*)d_in[3];  const float* bk = (const float*)d_in[4];
    const float* Wv = (const float*)d_in[5];  const float* bv = (const float*)d_in[6];
    const float* Wo = (const float*)d_in[7];  const float* bo = (const float*)d_in[8];
    const float* lng = (const float*)d_in[9]; const float* lnb = (const float*)d_in[10];
    const float* alpha = (const float*)d_in[11];
    float* out = (float*)d_out;

    k_prep<<<5120, 256>>>(hidden, Wq, Wk, Wv, Wo);
    k_qkv_mma<<<dim3(12, 64), 128>>>(bq, bk, bv);
    k_attn_fused<<<dim3(16, 32), 128>>>();
    k_out_mma<<<dim3(4, 64), 128>>>(bo);
    k_ln<<<8192, 256>>>(hidden, lng, lnb, alpha, out);
}

// round 14
// speedup vs baseline: 1.7485x; 1.0565x over previous
#include <cuda_runtime.h>
#include <cuda_bf16.h>
#include <stdint.h>
#include <math.h>

// Shapes (fixed): B=4, S=2, T=1024, D=512, H=8, HD=64, M = B*S*T = 8192
// bf16 tensor-core GEMMs (mma.sync m16n8k16, fp32 accum), 2-stage cp.async.
// Projection GEMMs use 256 threads / 8 warps (64x32 warp tiles) for occupancy.
// Fused attention: loop1 computes z locally, loop2 recomputes scores,
// normalizes + competitive-combines on the C->A repack, runs AV.
// Q carries 0.125*log2(e) so exp is bare ex2.approx.

// ---------------- device workspaces ----------------
__device__ __nv_bfloat16 g_Xh[8192ull * 512];
__device__ __nv_bfloat16 g_Wh[4ull * 512 * 512];  // [Wq;Wk;Wv;Wo]
__device__ __nv_bfloat16 g_Qh[8192ull * 512];     // Q * 0.125 * log2(e)
__device__ __nv_bfloat16 g_Kh[8192ull * 512];
__device__ __nv_bfloat16 g_Vh[8192ull * 512];
__device__ __nv_bfloat16 g_attnh[8192ull * 512];
__device__ float         g_proj[8192ull * 512];

// ---------------- helpers ----------------
__device__ __forceinline__ uint32_t pack_bf16x2(float a, float b) {
    __nv_bfloat162 h = __floats2bfloat162_rn(a, b);
    return *reinterpret_cast<uint32_t*>(&h);
}

__device__ __forceinline__ void mma16816(float* c, const uint32_t* a, uint32_t b0, uint32_t b1) {
    asm volatile(
        "mma.sync.aligned.m16n8k16.row.col.f32.bf16.bf16.f32 "
        "{%0,%1,%2,%3}, {%4,%5,%6,%7}, {%8,%9}, {%0,%1,%2,%3};\n"
        : "+f"(c[0]), "+f"(c[1]), "+f"(c[2]), "+f"(c[3])
        : "r"(a[0]), "r"(a[1]), "r"(a[2]), "r"(a[3]), "r"(b0), "r"(b1));
}

__device__ __forceinline__ void cpa16(void* smem, const void* g) {
    uint32_t s = (uint32_t)__cvta_generic_to_shared(smem);
    asm volatile("cp.async.cg.shared.global [%0], [%1], 16;" :: "r"(s), "l"(g));
}
#define CPA_COMMIT asm volatile("cp.async.commit_group;")
#define CPA_WAIT0  asm volatile("cp.async.wait_group 0;")

__device__ __forceinline__ float rcp_approx(float x) {
    float r;
    asm("rcp.approx.f32 %0, %1;" : "=f"(r) : "f"(x));
    return r;
}

__device__ __forceinline__ float ex2f(float x) {
    float r;
    asm("ex2.approx.f32 %0, %1;" : "=f"(r) : "f"(x));
    return r;
}

__device__ __forceinline__ float blk_red_sum(float v, float* sm) {
    int lane = threadIdx.x & 31, wid = threadIdx.x >> 5;
#pragma unroll
    for (int o = 16; o; o >>= 1) v += __shfl_xor_sync(0xffffffffu, v, o);
    if (lane == 0) sm[wid] = v;
    __syncthreads();
    float r = 0.f;
#pragma unroll
    for (int i = 0; i < 8; i++) r += sm[i];
    __syncthreads();
    return r;
}

// ---------------- 0) convert inputs to bf16 ----------------
__global__ __launch_bounds__(256) void k_prep(
    const float* __restrict__ X,
    const float* __restrict__ Wq, const float* __restrict__ Wk,
    const float* __restrict__ Wv, const float* __restrict__ Wo)
{
    const int idx = blockIdx.x * 256 + threadIdx.x;
    if (idx < 1048576) {
        float4 v = ((const float4*)X)[idx];
        uint2 o; o.x = pack_bf16x2(v.x, v.y); o.y = pack_bf16x2(v.z, v.w);
        ((uint2*)g_Xh)[idx] = o;
    } else {
        int j = idx - 1048576;
        int w = j >> 16;
        const float4* src = (w == 0) ? (const float4*)Wq : (w == 1) ? (const float4*)Wk
                          : (w == 2) ? (const float4*)Wv : (const float4*)Wo;
        float4 v = src[j & 65535];
        uint2 o; o.x = pack_bf16x2(v.x, v.y); o.y = pack_bf16x2(v.z, v.w);
        ((uint2*)g_Wh)[j] = o;
    }
}

// ---------------- 1) QKV projection: 256 thr, 8 warps (2x4), 64x32 warp tile ----
__global__ __launch_bounds__(256) void k_qkv_mma(
    const float* __restrict__ bq, const float* __restrict__ bk, const float* __restrict__ bv)
{
    __shared__ __nv_bfloat16 As[2][128][40];
    __shared__ __nv_bfloat16 Bs[2][128][40];
    const int tid = threadIdx.x, lane = tid & 31, warp = tid >> 5;
    const int wm = warp >> 2, wn = warp & 3;
    const int g = lane >> 2, t = lane & 3;
    const int m0 = blockIdx.y * 128, n0g = blockIdx.x * 128;

    const int lrow = tid >> 1, lseg = (tid & 1) * 16;
    const __nv_bfloat16* srcA0 = g_Xh + (size_t)(m0 + lrow) * 512 + lseg;
    const __nv_bfloat16* srcB0 = g_Wh + (size_t)(n0g + lrow) * 512 + lseg;

    float acc[4][4][4] = {};

#define QKV_ISSUE(K0, BUF)                                            \
    {                                                                 \
        cpa16(&As[BUF][lrow][lseg],     srcA0 + (K0));                \
        cpa16(&As[BUF][lrow][lseg + 8], srcA0 + (K0) + 8);            \
        cpa16(&Bs[BUF][lrow][lseg],     srcB0 + (K0));                \
        cpa16(&Bs[BUF][lrow][lseg + 8], srcB0 + (K0) + 8);            \
    }

    QKV_ISSUE(0, 0); CPA_COMMIT;

    for (int it = 0; it < 16; it++) {
        CPA_WAIT0;
        __syncthreads();
        if (it + 1 < 16) { QKV_ISSUE((it + 1) * 32, (it + 1) & 1); CPA_COMMIT; }
        const int cb = it & 1;
#pragma unroll
        for (int kk = 0; kk < 32; kk += 16) {
            uint32_t a[4][4];
#pragma unroll
            for (int mi = 0; mi < 4; mi++)
#pragma unroll
                for (int p = 0; p < 4; p++)
                    a[mi][p] = *(const uint32_t*)&As[cb][wm * 64 + mi * 16 + ((p & 1) << 3) + g]
                                                   [kk + 2 * t + ((p >> 1) << 3)];
#pragma unroll
            for (int ni = 0; ni < 4; ni++) {
                uint32_t b0 = *(const uint32_t*)&Bs[cb][wn * 32 + ni * 8 + g][kk + 2 * t];
                uint32_t b1 = *(const uint32_t*)&Bs[cb][wn * 32 + ni * 8 + g][kk + 2 * t + 8];
#pragma unroll
                for (int mi = 0; mi < 4; mi++) mma16816(acc[mi][ni], a[mi], b0, b1);
            }
        }
        __syncthreads();
    }
#undef QKV_ISSUE

    const int mat = n0g >> 9, nloc = n0g & 511;
    const float* bias = (mat == 0) ? bq : (mat == 1) ? bk : bv;
    __nv_bfloat16* out = (mat == 0) ? g_Qh : (mat == 1) ? g_Kh : g_Vh;
    // Q scale: 1/sqrt(64) * log2(e) so attention logits are base-2 ready.
    const float scale = (mat == 0) ? 0.125f * 1.4426950408889634f : 1.0f;

#pragma unroll
    for (int mi = 0; mi < 4; mi++) {
        int r0 = m0 + wm * 64 + mi * 16 + g;
#pragma unroll
        for (int ni = 0; ni < 4; ni++) {
            int col = nloc + wn * 32 + ni * 8 + 2 * t;
            float b0f = bias[col], b1f = bias[col + 1];
            *(uint32_t*)(out + (size_t)r0 * 512 + col) =
                pack_bf16x2((acc[mi][ni][0] + b0f) * scale, (acc[mi][ni][1] + b1f) * scale);
            *(uint32_t*)(out + (size_t)(r0 + 8) * 512 + col) =
                pack_bf16x2((acc[mi][ni][2] + b0f) * scale, (acc[mi][ni][3] + b1f) * scale);
        }
    }
}

// ---------------- 2) fused attention: rowsum pass + normalize+compete+AV ------
// grid (16, 32): x = 64-row q-tile, y = bh. 128 threads = 4 warps.
__global__ __launch_bounds__(128) void k_attn_fused()
{
    __shared__ __nv_bfloat16 K1s[2][32][72];
    __shared__ __nv_bfloat16 K2s[2][32][72];
    __shared__ __nv_bfloat16 V1s[2][64][40];   // [dim][tok]
    __shared__ __nv_bfloat16 V2s[2][64][40];

    const int bh = blockIdx.y, b = bh >> 3, h = bh & 7;
    const int m0 = blockIdx.x * 64;
    const __nv_bfloat16* Q1 = g_Qh + ((size_t)(b * 2 + 0) * 1024) * 512 + h * 64;
    const __nv_bfloat16* Q2 = g_Qh + ((size_t)(b * 2 + 1) * 1024) * 512 + h * 64;
    const __nv_bfloat16* K1 = g_Kh + ((size_t)(b * 2 + 0) * 1024) * 512 + h * 64;
    const __nv_bfloat16* K2 = g_Kh + ((size_t)(b * 2 + 1) * 1024) * 512 + h * 64;
    const __nv_bfloat16* V1 = g_Vh + ((size_t)(b * 2 + 0) * 1024) * 512 + h * 64;
    const __nv_bfloat16* V2 = g_Vh + ((size_t)(b * 2 + 1) * 1024) * 512 + h * 64;
    __nv_bfloat16* C1 = g_attnh + ((size_t)(b * 2 + 0) * 1024) * 512 + h * 64;  // A12 @ V2
    __nv_bfloat16* C2 = g_attnh + ((size_t)(b * 2 + 1) * 1024) * 512 + h * 64;  // A21 @ V1

    const int tid = threadIdx.x, lane = tid & 31, warp = tid >> 5;
    const int g = lane >> 2, t = lane & 3;

    // Q A-fragments, held in registers for the whole kernel.
    uint32_t qa1[4][4], qa2[4][4];
#pragma unroll
    for (int kc = 0; kc < 4; kc++)
#pragma unroll
        for (int p = 0; p < 4; p++) {
            const int row = m0 + warp * 16 + ((p & 1) << 3) + g;
            const int col = kc * 16 + ((p >> 1) << 3) + 2 * t;
            qa1[kc][p] = *(const uint32_t*)(Q1 + (size_t)row * 512 + col);
            qa2[kc][p] = *(const uint32_t*)(Q2 + (size_t)row * 512 + col);
        }

    // K/V tile load mappings: 32 rows (tokens) x 4 segments of 16 bf16
    const int krow = tid >> 2, kseg = (tid & 3) * 16;
    const __nv_bfloat16* srcK1 = K1 + (size_t)krow * 512 + kseg;
    const __nv_bfloat16* srcK2 = K2 + (size_t)krow * 512 + kseg;
    const __nv_bfloat16* srcV1 = V1 + (size_t)krow * 512 + kseg;
    const __nv_bfloat16* srcV2 = V2 + (size_t)krow * 512 + kseg;

#define ATT_ISSUE_K(K0, BUF)                                              \
    {                                                                     \
        cpa16(&K1s[BUF][krow][kseg],     srcK1 + (size_t)(K0) * 512);     \
        cpa16(&K1s[BUF][krow][kseg + 8], srcK1 + (size_t)(K0) * 512 + 8); \
        cpa16(&K2s[BUF][krow][kseg],     srcK2 + (size_t)(K0) * 512);     \
        cpa16(&K2s[BUF][krow][kseg + 8], srcK2 + (size_t)(K0) * 512 + 8); \
    }

    // ================= loop 1: row sums z (K only) =================
    float z1a = 0.f, z1b = 0.f, z2a = 0.f, z2b = 0.f;

    ATT_ISSUE_K(0, 0); CPA_COMMIT;
    for (int it = 0; it < 32; it++) {
        CPA_WAIT0;
        __syncthreads();
        if (it + 1 < 32) { ATT_ISSUE_K((it + 1) * 32, (it + 1) & 1); CPA_COMMIT; }
        const int cb = it & 1;
#pragma unroll
        for (int nb = 0; nb < 4; nb++) {
            float c12[4] = {}, c21[4] = {};
#pragma unroll
            for (int kc = 0; kc < 4; kc++) {
                uint32_t b0 = *(const uint32_t*)&K2s[cb][nb * 8 + g][kc * 16 + 2 * t];
                uint32_t b1 = *(const uint32_t*)&K2s[cb][nb * 8 + g][kc * 16 + 2 * t + 8];
                mma16816(c12, qa1[kc], b0, b1);
                uint32_t d0 = *(const uint32_t*)&K1s[cb][nb * 8 + g][kc * 16 + 2 * t];
                uint32_t d1 = *(const uint32_t*)&K1s[cb][nb * 8 + g][kc * 16 + 2 * t + 8];
                mma16816(c21, qa2[kc], d0, d1);
            }
            z1a += ex2f(c12[0]) + ex2f(c12[1]);
            z1b += ex2f(c12[2]) + ex2f(c12[3]);
            z2a += ex2f(c21[0]) + ex2f(c21[1]);
            z2b += ex2f(c21[2]) + ex2f(c21[3]);
        }
        __syncthreads();
    }
#pragma unroll
    for (int o = 1; o < 4; o <<= 1) {
        z1a += __shfl_xor_sync(0xffffffffu, z1a, o);
        z1b += __shfl_xor_sync(0xffffffffu, z1b, o);
        z2a += __shfl_xor_sync(0xffffffffu, z2a, o);
        z2b += __shfl_xor_sync(0xffffffffu, z2b, o);
    }
    const float i1a = __fdividef(1.f, z1a), i1b = __fdividef(1.f, z1b);
    const float i2a = __fdividef(1.f, z2a), i2b = __fdividef(1.f, z2b);

    // ================= loop 2: normalize + compete + AV =================
    float o1[8][4] = {}, o2[8][4] = {};
    __nv_bfloat16 vr1[16], vr2[16];

#define ATT_LD_V(K0)                                                  \
    {                                                                 \
        const __nv_bfloat16* s1 = srcV1 + (size_t)(K0) * 512;         \
        const __nv_bfloat16* s2 = srcV2 + (size_t)(K0) * 512;         \
        *(uint4*)vr1       = *(const uint4*)s1;                       \
        *(uint4*)(vr1 + 8) = *(const uint4*)(s1 + 8);                 \
        *(uint4*)vr2       = *(const uint4*)s2;                       \
        *(uint4*)(vr2 + 8) = *(const uint4*)(s2 + 8);                 \
    }
#define ATT_ST_V(BUF)                                                 \
    {                                                                 \
        _Pragma("unroll")                                             \
        for (int j = 0; j < 16; j++) {                                \
            V1s[BUF][kseg + j][krow] = vr1[j];                        \
            V2s[BUF][kseg + j][krow] = vr2[j];                        \
        }                                                             \
    }

    ATT_ISSUE_K(0, 0); CPA_COMMIT;
    ATT_LD_V(0); ATT_ST_V(0);
    ATT_LD_V(32);

    for (int it = 0; it < 32; it++) {
        CPA_WAIT0;
        __syncthreads();
        if (it + 1 < 32) { ATT_ISSUE_K((it + 1) * 32, (it + 1) & 1); CPA_COMMIT; }
        const int cb = it & 1;

        uint32_t na1[2][4], na2[2][4];   // AV A-frags [kc2][p]
#pragma unroll
        for (int nb = 0; nb < 4; nb++) {
            float c12[4] = {}, c21[4] = {};
#pragma unroll
            for (int kc = 0; kc < 4; kc++) {
                uint32_t b0 = *(const uint32_t*)&K2s[cb][nb * 8 + g][kc * 16 + 2 * t];
                uint32_t b1 = *(const uint32_t*)&K2s[cb][nb * 8 + g][kc * 16 + 2 * t + 8];
                mma16816(c12, qa1[kc], b0, b1);
                uint32_t d0 = *(const uint32_t*)&K1s[cb][nb * 8 + g][kc * 16 + 2 * t];
                uint32_t d1 = *(const uint32_t*)&K1s[cb][nb * 8 + g][kc * 16 + 2 * t + 8];
                mma16816(c21, qa2[kc], d0, d1);
            }
            float s10 = ex2f(c12[0]) * i1a, s11 = ex2f(c12[1]) * i1a;
            float s12f = ex2f(c12[2]) * i1b, s13 = ex2f(c12[3]) * i1b;
            float s20 = ex2f(c21[0]) * i2a, s21f = ex2f(c21[1]) * i2a;
            float s22 = ex2f(c21[2]) * i2b, s23 = ex2f(c21[3]) * i2b;
            float d0 = s10 + s20 + 1e-6f, d1 = s11 + s21f + 1e-6f;
            float d2 = s12f + s22 + 1e-6f, d3 = s13 + s23 + 1e-6f;
            float ra = rcp_approx(d0 * d1);
            float rb = rcp_approx(d2 * d3);
            float inv0 = ra * d1, inv1 = ra * d0;
            float inv2 = rb * d3, inv3 = rb * d2;
            const int kc2 = nb >> 1, pb = (nb & 1) << 1;
            na1[kc2][pb]     = pack_bf16x2(s10 * inv0, s11 * inv1);
            na1[kc2][pb + 1] = pack_bf16x2(s12f * inv2, s13 * inv3);
            na2[kc2][pb]     = pack_bf16x2(s20 * inv0, s21f * inv1);
            na2[kc2][pb + 1] = pack_bf16x2(s22 * inv2, s23 * inv3);
        }

#pragma unroll
        for (int nd = 0; nd < 8; nd++) {
            const int cbase = nd * 8 + g;
#pragma unroll
            for (int kc2 = 0; kc2 < 2; kc2++) {
                uint32_t b20 = *(const uint32_t*)&V2s[cb][cbase][kc2 * 16 + 2 * t];
                uint32_t b21 = *(const uint32_t*)&V2s[cb][cbase][kc2 * 16 + 2 * t + 8];
                mma16816(o1[nd], na1[kc2], b20, b21);
                uint32_t b10 = *(const uint32_t*)&V1s[cb][cbase][kc2 * 16 + 2 * t];
                uint32_t b11 = *(const uint32_t*)&V1s[cb][cbase][kc2 * 16 + 2 * t + 8];
                mma16816(o2[nd], na2[kc2], b10, b11);
            }
        }

        if (it + 1 < 32) {
            ATT_ST_V((it + 1) & 1);
            if (it + 2 < 32) ATT_LD_V((it + 2) * 32);
        }
    }
#undef ATT_ISSUE_K
#undef ATT_LD_V
#undef ATT_ST_V

    const int r0 = m0 + warp * 16 + g;
#pragma unroll
    for (int nd = 0; nd < 8; nd++) {
        int col = nd * 8 + 2 * t;
        *(uint32_t*)(C1 + (size_t)r0 * 512 + col)       = pack_bf16x2(o1[nd][0], o1[nd][1]);
        *(uint32_t*)(C1 + (size_t)(r0 + 8) * 512 + col) = pack_bf16x2(o1[nd][2], o1[nd][3]);
        *(uint32_t*)(C2 + (size_t)r0 * 512 + col)       = pack_bf16x2(o2[nd][0], o2[nd][1]);
        *(uint32_t*)(C2 + (size_t)(r0 + 8) * 512 + col) = pack_bf16x2(o2[nd][2], o2[nd][3]);
    }
}

// ---------------- 3) output projection: 256 thr, 8 warps (2x4), 64x32 warp tile ----
__global__ __launch_bounds__(256) void k_out_mma(const float* __restrict__ bo)
{
    __shared__ __nv_bfloat16 As[2][128][40];
    __shared__ __nv_bfloat16 Bs[2][128][40];
    const int tid = threadIdx.x, lane = tid & 31, warp = tid >> 5;
    const int wm = warp >> 2, wn = warp & 3;
    const int g = lane >> 2, t = lane & 3;
    const int m0 = blockIdx.y * 128, n0 = blockIdx.x * 128;
    const __nv_bfloat16* Wo = g_Wh + 3ull * 512 * 512;

    const int lrow = tid >> 1, lseg = (tid & 1) * 16;
    const __nv_bfloat16* srcA0 = g_attnh + (size_t)(m0 + lrow) * 512 + lseg;
    const __nv_bfloat16* srcB0 = Wo + (size_t)(n0 + lrow) * 512 + lseg;

    float acc[4][4][4] = {};

#define OUT_ISSUE(K0, BUF)                                            \
    {                                                                 \
        cpa16(&As[BUF][lrow][lseg],     srcA0 + (K0));                \
        cpa16(&As[BUF][lrow][lseg + 8], srcA0 + (K0) + 8);            \
        cpa16(&Bs[BUF][lrow][lseg],     srcB0 + (K0));                \
        cpa16(&Bs[BUF][lrow][lseg + 8], srcB0 + (K0) + 8);            \
    }

    OUT_ISSUE(0, 0); CPA_COMMIT;

    for (int it = 0; it < 16; it++) {
        CPA_WAIT0;
        __syncthreads();
        if (it + 1 < 16) { OUT_ISSUE((it + 1) * 32, (it + 1) & 1); CPA_COMMIT; }
        const int cb = it & 1;
#pragma unroll
        for (int kk = 0; kk < 32; kk += 16) {
            uint32_t a[4][4];
#pragma unroll
            for (int mi = 0; mi < 4; mi++)
#pragma unroll
                for (int p = 0; p < 4; p++)
                    a[mi][p] = *(const uint32_t*)&As[cb][wm * 64 + mi * 16 + ((p & 1) << 3) + g]
                                                   [kk + 2 * t + ((p >> 1) << 3)];
#pragma unroll
            for (int ni = 0; ni < 4; ni++) {
                uint32_t b0 = *(const uint32_t*)&Bs[cb][wn * 32 + ni * 8 + g][kk + 2 * t];
                uint32_t b1 = *(const uint32_t*)&Bs[cb][wn * 32 + ni * 8 + g][kk + 2 * t + 8];
#pragma unroll
                for (int mi = 0; mi < 4; mi++) mma16816(acc[mi][ni], a[mi], b0, b1);
            }
        }
        __syncthreads();
    }
#undef OUT_ISSUE

#pragma unroll
    for (int mi = 0; mi < 4; mi++) {
        int r0 = m0 + wm * 64 + mi * 16 + g;
#pragma unroll
        for (int ni = 0; ni < 4; ni++) {
            int col = n0 + wn * 32 + ni * 8 + 2 * t;
            float b0f = bo[col], b1f = bo[col + 1];
            *(float2*)(g_proj + (size_t)r0 * 512 + col) =
                make_float2(acc[mi][ni][0] + b0f, acc[mi][ni][1] + b1f);
            *(float2*)(g_proj + (size_t)(r0 + 8) * 512 + col) =
                make_float2(acc[mi][ni][2] + b0f, acc[mi][ni][3] + b1f);
        }
    }
}

// ---------------- 4) LayerNorm + gate + residual ----------------
__global__ __launch_bounds__(256) void k_ln(
    const float* __restrict__ hidden,
    const float* __restrict__ ln_g, const float* __restrict__ ln_b,
    const float* __restrict__ alpha, float* __restrict__ out)
{
    const int m = blockIdx.x;
    const int s = (m >> 10) & 1;
    const float* p = g_proj + (size_t)m * 512;
    const int tid = threadIdx.x;
    __shared__ float sm[8];

    float x0 = p[tid], x1 = p[tid + 256];
    float sum = blk_red_sum(x0 + x1, sm);
    float sq  = blk_red_sum(x0 * x0 + x1 * x1, sm);
    float mu  = sum * (1.f / 512.f);
    float var = sq * (1.f / 512.f) - mu * mu;
    float rstd = rsqrtf(var + 1e-5f);
    float al = alpha[s];
    size_t base = (size_t)m * 512;

    {
        int e = tid;
        float y = (x0 - mu) * rstd * ln_g[s * 512 + e] + ln_b[s * 512 + e];
        out[base + e] = hidden[base + e] + y * al;
    }
    {
        int e = tid + 256;
        float y = (x1 - mu) * rstd * ln_g[s * 512 + e] + ln_b[s * 512 + e];
        out[base + e] = hidden[base + e] + y * al;
    }
}

// ---------------- launch ----------------
extern "C" void kernel_launch(void* const* d_in, const int* in_sizes, int n_in,
                              void* d_out, int out_size)
{
    const float* hidden = (const float*)d_in[0];
    const float* Wq = (const float*)d_in[1];  const float* bq = (const float*)d_in[2];
    const float* Wk = (const float*)d_in[3];  const float* bk = (const float*)d_in[4];
    const float* Wv = (const float*)d_in[5];  const float* bv = (const float*)d_in[6];
    const float* Wo = (const float*)d_in[7];  const float* bo = (const float*)d_in[8];
    const float* lng = (const float*)d_in[9]; const float* lnb = (const float*)d_in[10];
    const float* alpha = (const float*)d_in[11];
    float* out = (float*)d_out;

    k_prep<<<5120, 256>>>(hidden, Wq, Wk, Wv, Wo);
    k_qkv_mma<<<dim3(12, 64), 256>>>(bq, bk, bv);
    k_attn_fused<<<dim3(16, 32), 128>>>();
    k_out_mma<<<dim3(4, 64), 256>>>(bo);
    k_ln<<<8192, 256>>>(hidden, lng, lnb, alpha, out);
}